// round 2
// baseline (speedup 1.0000x reference)
#include <cuda_runtime.h>
#include <cstdint>
#include <cstddef>

// Problem dims (fixed)
#define BB   2
#define SS   2048
#define TT   2048
#define DD   512
#define HH   8
#define DKK  64
#define FFF  2048

#define NSD  (BB*SS*DD)              // 2,097,152 floats
#define NSF  (BB*SS*FFF)             // 8,388,608 floats
#define AW_ELEMS ((size_t)BB*HH*(size_t)SS*TT)  // 67,108,864 floats

// Scratch: q,k,v,attn,ybuf,o1,o2 (7*NSD) + ffn hidden (NSF)  ~= 92 MB
__device__ float g_scratch[7*NSD + NSF];

// ---------------------------------------------------------------------------
// Generic 64x64 tiled SGEMM: C[M,N] = A[M,K] @ B[K,N] (+bias) (+res) (relu)
// Grid: (N/64, M/64). All dims are multiples of 64/16 -> no bounds checks.
// ---------------------------------------------------------------------------
__global__ __launch_bounds__(256) void sgemm_kernel(
    const float* __restrict__ A, int lda,
    const float* __restrict__ B, int ldb,
    float* __restrict__ C, int ldc,
    const float* __restrict__ bias,
    const float* __restrict__ res, int ldr,
    int K, int relu)
{
    __shared__ float As[16][68];
    __shared__ float Bs[16][68];
    const int tid = threadIdx.x;
    const int tx = tid & 15, ty = tid >> 4;
    const int row0 = blockIdx.y * 64, col0 = blockIdx.x * 64;

    float acc[4][4] = {};
    for (int k0 = 0; k0 < K; k0 += 16) {
        #pragma unroll
        for (int i = 0; i < 4; i++) {
            int idx = tid + i*256;
            int ra = idx >> 4, ca = idx & 15;
            As[ca][ra] = A[(size_t)(row0+ra)*lda + k0 + ca];
            int rb = idx >> 6, cb = idx & 63;
            Bs[rb][cb] = B[(size_t)(k0+rb)*ldb + col0 + cb];
        }
        __syncthreads();
        #pragma unroll
        for (int kk = 0; kk < 16; kk++) {
            float4 a4 = *(const float4*)&As[kk][ty*4];
            float4 b4 = *(const float4*)&Bs[kk][tx*4];
            float ar[4] = {a4.x, a4.y, a4.z, a4.w};
            float br[4] = {b4.x, b4.y, b4.z, b4.w};
            #pragma unroll
            for (int i = 0; i < 4; i++)
                #pragma unroll
                for (int j = 0; j < 4; j++)
                    acc[i][j] += ar[i]*br[j];
        }
        __syncthreads();
    }
    #pragma unroll
    for (int i = 0; i < 4; i++) {
        int r = row0 + ty*4 + i;
        #pragma unroll
        for (int j = 0; j < 4; j++) {
            int c = col0 + tx*4 + j;
            float v = acc[i][j];
            if (bias) v += bias[c];
            if (res)  v += res[(size_t)r*ldr + c];
            if (relu) v = fmaxf(v, 0.f);
            C[(size_t)r*ldc + c] = v;
        }
    }
}

// ---------------------------------------------------------------------------
// Attention logits: AW[b,h,i,j] = (Q_h[i,:] . K_h[j,:]) * 0.125  (- 1e9 if causal & j>i)
// Grid: (T/64, S/64, B*H)
// ---------------------------------------------------------------------------
__global__ __launch_bounds__(256) void logits_kernel(
    const float* __restrict__ Q, const float* __restrict__ Km,
    float* __restrict__ AW, int causal)
{
    const int z = blockIdx.z;
    const int b = z >> 3, h = z & 7;
    const float* Aq = Q  + (size_t)b*SS*DD + h*DKK;
    const float* Bk = Km + (size_t)b*TT*DD + h*DKK;
    float* Cw = AW + (size_t)z*SS*TT;
    const int tid = threadIdx.x;
    const int tx = tid & 15, ty = tid >> 4;
    const int row0 = blockIdx.y*64, col0 = blockIdx.x*64;

    if (causal && col0 > row0 + 63) {
        // fully masked tile: softmax maps it to exactly 0 either way
        #pragma unroll
        for (int i = 0; i < 4; i++) {
            int r = row0 + ty*4 + i;
            #pragma unroll
            for (int j = 0; j < 4; j++)
                Cw[(size_t)r*TT + col0 + tx*4 + j] = -1e9f;
        }
        return;
    }

    __shared__ float As[16][68];
    __shared__ float Bs[16][68];
    float acc[4][4] = {};
    #pragma unroll
    for (int k0 = 0; k0 < DKK; k0 += 16) {
        #pragma unroll
        for (int i = 0; i < 4; i++) {
            int idx = tid + i*256;
            int r = idx >> 4, c = idx & 15;
            As[c][r] = Aq[(size_t)(row0+r)*DD + k0 + c];
            Bs[c][r] = Bk[(size_t)(col0+r)*DD + k0 + c];
        }
        __syncthreads();
        #pragma unroll
        for (int kk = 0; kk < 16; kk++) {
            float4 a4 = *(const float4*)&As[kk][ty*4];
            float4 b4 = *(const float4*)&Bs[kk][tx*4];
            float ar[4] = {a4.x, a4.y, a4.z, a4.w};
            float br[4] = {b4.x, b4.y, b4.z, b4.w};
            #pragma unroll
            for (int i = 0; i < 4; i++)
                #pragma unroll
                for (int j = 0; j < 4; j++)
                    acc[i][j] += ar[i]*br[j];
        }
        __syncthreads();
    }
    #pragma unroll
    for (int i = 0; i < 4; i++) {
        int r = row0 + ty*4 + i;
        #pragma unroll
        for (int j = 0; j < 4; j++) {
            int c = col0 + tx*4 + j;
            float v = acc[i][j] * 0.125f;
            if (causal && c > r) v -= 1e9f;
            Cw[(size_t)r*TT + c] = v;
        }
    }
}

// ---------------------------------------------------------------------------
// Row softmax in place. One block per row (length TT=2048), 256 threads.
// ---------------------------------------------------------------------------
__global__ __launch_bounds__(256) void softmax_kernel(float* __restrict__ AW)
{
    const int tid = threadIdx.x;
    float4* r4 = (float4*)(AW + (size_t)blockIdx.x * TT);
    float4 v0 = r4[tid];
    float4 v1 = r4[tid + 256];

    float m = fmaxf(fmaxf(fmaxf(v0.x,v0.y),fmaxf(v0.z,v0.w)),
                    fmaxf(fmaxf(v1.x,v1.y),fmaxf(v1.z,v1.w)));
    #pragma unroll
    for (int o = 16; o > 0; o >>= 1) m = fmaxf(m, __shfl_xor_sync(0xffffffffu, m, o));
    __shared__ float red[8];
    if ((tid & 31) == 0) red[tid >> 5] = m;
    __syncthreads();
    float bm = red[0];
    #pragma unroll
    for (int i = 1; i < 8; i++) bm = fmaxf(bm, red[i]);
    __syncthreads();

    v0.x = __expf(v0.x - bm); v0.y = __expf(v0.y - bm);
    v0.z = __expf(v0.z - bm); v0.w = __expf(v0.w - bm);
    v1.x = __expf(v1.x - bm); v1.y = __expf(v1.y - bm);
    v1.z = __expf(v1.z - bm); v1.w = __expf(v1.w - bm);
    float s = v0.x+v0.y+v0.z+v0.w + v1.x+v1.y+v1.z+v1.w;
    #pragma unroll
    for (int o = 16; o > 0; o >>= 1) s += __shfl_xor_sync(0xffffffffu, s, o);
    if ((tid & 31) == 0) red[tid >> 5] = s;
    __syncthreads();
    float bs = 0.f;
    #pragma unroll
    for (int i = 0; i < 8; i++) bs += red[i];
    float inv = 1.f / bs;

    v0.x *= inv; v0.y *= inv; v0.z *= inv; v0.w *= inv;
    v1.x *= inv; v1.y *= inv; v1.z *= inv; v1.w *= inv;
    r4[tid] = v0;
    r4[tid + 256] = v1;
}

// ---------------------------------------------------------------------------
// AV: O[b, i, h*64+d] = sum_j AW[b,h,i,j] * V[b, j, h*64+d]
// Grid: (1, S/64, B*H). N = 64 (one tile).
// ---------------------------------------------------------------------------
__global__ __launch_bounds__(256) void av_kernel(
    const float* __restrict__ AW, const float* __restrict__ V,
    float* __restrict__ O)
{
    const int z = blockIdx.z, b = z >> 3, h = z & 7;
    const float* Aa = AW + (size_t)z*SS*TT;          // lda = TT
    const float* Bv = V + (size_t)b*TT*DD + h*DKK;   // ldb = DD
    float* Co = O + (size_t)b*SS*DD + h*DKK;         // ldc = DD
    const int tid = threadIdx.x;
    const int tx = tid & 15, ty = tid >> 4;
    const int row0 = blockIdx.y * 64;

    __shared__ float As[16][68];
    __shared__ float Bs[16][68];
    float acc[4][4] = {};
    for (int k0 = 0; k0 < TT; k0 += 16) {
        #pragma unroll
        for (int i = 0; i < 4; i++) {
            int idx = tid + i*256;
            int ra = idx >> 4, ca = idx & 15;
            As[ca][ra] = Aa[(size_t)(row0+ra)*TT + k0 + ca];
            int rb = idx >> 6, cb = idx & 63;
            Bs[rb][cb] = Bv[(size_t)(k0+rb)*DD + cb];
        }
        __syncthreads();
        #pragma unroll
        for (int kk = 0; kk < 16; kk++) {
            float4 a4 = *(const float4*)&As[kk][ty*4];
            float4 b4 = *(const float4*)&Bs[kk][tx*4];
            float ar[4] = {a4.x, a4.y, a4.z, a4.w};
            float br[4] = {b4.x, b4.y, b4.z, b4.w};
            #pragma unroll
            for (int i = 0; i < 4; i++)
                #pragma unroll
                for (int j = 0; j < 4; j++)
                    acc[i][j] += ar[i]*br[j];
        }
        __syncthreads();
    }
    #pragma unroll
    for (int i = 0; i < 4; i++) {
        int r = row0 + ty*4 + i;
        #pragma unroll
        for (int j = 0; j < 4; j++)
            Co[(size_t)r*DD + tx*4 + j] = acc[i][j];
    }
}

// ---------------------------------------------------------------------------
// LayerNorm over D=512. One block per row, 128 threads (float4 each).
// ---------------------------------------------------------------------------
__global__ __launch_bounds__(128) void ln_kernel(
    const float* __restrict__ X, const float* __restrict__ g,
    const float* __restrict__ be, float* __restrict__ O)
{
    const int tid = threadIdx.x;
    const float4* x4 = (const float4*)(X + (size_t)blockIdx.x * DD);
    float4 xv = x4[tid];
    float s  = xv.x + xv.y + xv.z + xv.w;
    float sq = xv.x*xv.x + xv.y*xv.y + xv.z*xv.z + xv.w*xv.w;
    #pragma unroll
    for (int o = 16; o > 0; o >>= 1) {
        s  += __shfl_xor_sync(0xffffffffu, s,  o);
        sq += __shfl_xor_sync(0xffffffffu, sq, o);
    }
    __shared__ float ss[4], ssq[4];
    if ((tid & 31) == 0) { ss[tid >> 5] = s; ssq[tid >> 5] = sq; }
    __syncthreads();
    s  = ss[0]  + ss[1]  + ss[2]  + ss[3];
    sq = ssq[0] + ssq[1] + ssq[2] + ssq[3];
    const float invD = 1.f / DD;
    float m = s * invD;
    float var = sq * invD - m*m;
    float rstd = rsqrtf(var + 1e-6f);
    float4 gv = ((const float4*)g)[tid];
    float4 bv = ((const float4*)be)[tid];
    float4 o;
    o.x = (xv.x - m)*rstd*gv.x + bv.x;
    o.y = (xv.y - m)*rstd*gv.y + bv.y;
    o.z = (xv.z - m)*rstd*gv.z + bv.z;
    o.w = (xv.w - m)*rstd*gv.w + bv.w;
    ((float4*)(O + (size_t)blockIdx.x * DD))[tid] = o;
}

// ---------------------------------------------------------------------------
// Host side
// ---------------------------------------------------------------------------
static float* scratch_ptr() {
    static float* p = nullptr;
    if (!p) cudaGetSymbolAddress((void**)&p, g_scratch);
    return p;
}

extern "C" void kernel_launch(void* const* d_in, const int* in_sizes, int n_in,
                              void* d_out, int out_size)
{
    const float* x   = (const float*)d_in[0];
    const float* enc = (const float*)d_in[1];
    // d_in[2] = look_ahead_mask (causal; applied analytically)
    const float* wq1 = (const float*)d_in[3];  const float* bq1 = (const float*)d_in[4];
    const float* wk1 = (const float*)d_in[5];  const float* bk1 = (const float*)d_in[6];
    const float* wv1 = (const float*)d_in[7];  const float* bv1 = (const float*)d_in[8];
    const float* wo1 = (const float*)d_in[9];  const float* bo1 = (const float*)d_in[10];
    const float* wq2 = (const float*)d_in[11]; const float* bq2 = (const float*)d_in[12];
    const float* wk2 = (const float*)d_in[13]; const float* bk2 = (const float*)d_in[14];
    const float* wv2 = (const float*)d_in[15]; const float* bv2 = (const float*)d_in[16];
    const float* wo2 = (const float*)d_in[17]; const float* bo2 = (const float*)d_in[18];
    const float* wf1 = (const float*)d_in[19]; const float* bf1 = (const float*)d_in[20];
    const float* wf2 = (const float*)d_in[21]; const float* bf2 = (const float*)d_in[22];
    const float* g1  = (const float*)d_in[23]; const float* be1 = (const float*)d_in[24];
    const float* g2  = (const float*)d_in[25]; const float* be2 = (const float*)d_in[26];
    const float* g3  = (const float*)d_in[27]; const float* be3 = (const float*)d_in[28];

    float* scr  = scratch_ptr();
    float* q    = scr;
    float* k    = q    + NSD;
    float* v    = k    + NSD;
    float* attn = v    + NSD;
    float* ybuf = attn + NSD;
    float* o1   = ybuf + NSD;
    float* o2   = o1   + NSD;
    float* hh   = o2   + NSD;

    float* out3 = (float*)d_out;
    float* aw1  = out3 + NSD;        // [B,H,S,T]
    float* aw2  = aw1  + AW_ELEMS;   // [B,H,S,T]

    dim3 thr(256);
    dim3 gProj(DD/64,  BB*SS/64);        // (8, 64)
    dim3 gLog (TT/64,  SS/64, BB*HH);    // (32, 32, 16)
    dim3 gAv  (1,      SS/64, BB*HH);    // (1, 32, 16)
    dim3 gFf1 (FFF/64, BB*SS/64);        // (32, 64)
    dim3 gFf2 (DD/64,  BB*SS/64);        // (8, 64)

    // ---- self-attention (causal) ----
    sgemm_kernel<<<gProj, thr>>>(x, DD, wq1, DD, q, DD, bq1, nullptr, 0, DD, 0);
    sgemm_kernel<<<gProj, thr>>>(x, DD, wk1, DD, k, DD, bk1, nullptr, 0, DD, 0);
    sgemm_kernel<<<gProj, thr>>>(x, DD, wv1, DD, v, DD, bv1, nullptr, 0, DD, 0);
    logits_kernel<<<gLog, thr>>>(q, k, aw1, 1);
    softmax_kernel<<<BB*HH*SS, 256>>>(aw1);
    av_kernel<<<gAv, thr>>>(aw1, v, attn);
    sgemm_kernel<<<gProj, thr>>>(attn, DD, wo1, DD, ybuf, DD, bo1, x, DD, DD, 0);
    ln_kernel<<<BB*SS, 128>>>(ybuf, g1, be1, o1);

    // ---- cross-attention (no mask) ----
    sgemm_kernel<<<gProj, thr>>>(o1,  DD, wq2, DD, q, DD, bq2, nullptr, 0, DD, 0);
    sgemm_kernel<<<gProj, thr>>>(enc, DD, wk2, DD, k, DD, bk2, nullptr, 0, DD, 0);
    sgemm_kernel<<<gProj, thr>>>(enc, DD, wv2, DD, v, DD, bv2, nullptr, 0, DD, 0);
    logits_kernel<<<gLog, thr>>>(q, k, aw2, 0);
    softmax_kernel<<<BB*HH*SS, 256>>>(aw2);
    av_kernel<<<gAv, thr>>>(aw2, v, attn);
    sgemm_kernel<<<gProj, thr>>>(attn, DD, wo2, DD, ybuf, DD, bo2, o1, DD, DD, 0);
    ln_kernel<<<BB*SS, 128>>>(ybuf, g2, be2, o2);

    // ---- FFN ----
    sgemm_kernel<<<gFf1, thr>>>(o2, DD, wf1, FFF, hh, FFF, bf1, nullptr, 0, DD, 1);
    sgemm_kernel<<<gFf2, thr>>>(hh, FFF, wf2, DD, ybuf, DD, bf2, o2, DD, FFF, 0);
    ln_kernel<<<BB*SS, 128>>>(ybuf, g3, be3, out3);
}

// round 3
// speedup vs baseline: 1.3275x; 1.3275x over previous
#include <cuda_runtime.h>
#include <cstdint>
#include <cstddef>

// Problem dims (fixed)
#define BB   2
#define SS   2048
#define TT   2048
#define DD   512
#define HH   8
#define DKK  64
#define FFF  2048

#define NSD  (BB*SS*DD)              // 2,097,152 floats
#define NSF  (BB*SS*FFF)             // 8,388,608 floats
#define AW_ELEMS ((size_t)BB*HH*(size_t)SS*TT)  // 67,108,864 floats

__device__ float g_scratch[7*NSD + NSF];

// ---------------------------------------------------------------------------
// SGEMM 128x64 block tile, 256 threads, 8x4 micro-tile, register prefetch.
// C[M,N] = A[M,K] @ B[K,N] (+bias)(+res)(relu). M%128==0, N%64==0, K%16==0.
// Grid: (N/64, M/128)
// ---------------------------------------------------------------------------
__global__ __launch_bounds__(256) void sgemm_kernel(
    const float* __restrict__ A, int lda,
    const float* __restrict__ B, int ldb,
    float* __restrict__ C, int ldc,
    const float* __restrict__ bias,
    const float* __restrict__ res, int ldr,
    int K, int relu)
{
    __shared__ float As[16][132];   // transposed: As[k][m]
    __shared__ float Bs[16][68];    // Bs[k][n]
    const int tid = threadIdx.x;
    const int tx = tid & 15;        // n dir (16 * 4 = 64)
    const int ty = tid >> 4;        // m dir (16 * 8 = 128)
    const int row0 = blockIdx.y * 128, col0 = blockIdx.x * 64;

    const int ar = tid >> 1, ak = (tid & 1) * 8;        // A: 128 rows x 16 k
    const int br = tid >> 4, bc = (tid & 15) * 4;       // B: 16 k x 64 n

    const float* Aptr = A + (size_t)(row0 + ar) * lda + ak;
    const float* Bptr = B + (size_t)br * ldb + col0 + bc;

    float4 pa0 = *(const float4*)(Aptr);
    float4 pa1 = *(const float4*)(Aptr + 4);
    float4 pb  = *(const float4*)(Bptr);

    float acc[8][4] = {};
    for (int k0 = 0; k0 < K; k0 += 16) {
        As[ak+0][ar]=pa0.x; As[ak+1][ar]=pa0.y; As[ak+2][ar]=pa0.z; As[ak+3][ar]=pa0.w;
        As[ak+4][ar]=pa1.x; As[ak+5][ar]=pa1.y; As[ak+6][ar]=pa1.z; As[ak+7][ar]=pa1.w;
        *(float4*)&Bs[br][bc] = pb;
        __syncthreads();
        if (k0 + 16 < K) {
            pa0 = *(const float4*)(Aptr + k0 + 16);
            pa1 = *(const float4*)(Aptr + k0 + 20);
            pb  = *(const float4*)(Bptr + (size_t)(k0 + 16) * ldb);
        }
        #pragma unroll
        for (int kk = 0; kk < 16; kk++) {
            float4 a0 = *(const float4*)&As[kk][ty*8];
            float4 a1 = *(const float4*)&As[kk][ty*8+4];
            float4 b  = *(const float4*)&Bs[kk][tx*4];
            float am[8] = {a0.x,a0.y,a0.z,a0.w,a1.x,a1.y,a1.z,a1.w};
            float bn[4] = {b.x,b.y,b.z,b.w};
            #pragma unroll
            for (int i = 0; i < 8; i++)
                #pragma unroll
                for (int j = 0; j < 4; j++)
                    acc[i][j] += am[i]*bn[j];
        }
        __syncthreads();
    }
    const int c = col0 + tx*4;
    float4 bi = bias ? *(const float4*)&bias[c] : make_float4(0,0,0,0);
    #pragma unroll
    for (int i = 0; i < 8; i++) {
        int r = row0 + ty*8 + i;
        float4 o;
        o.x = acc[i][0] + bi.x; o.y = acc[i][1] + bi.y;
        o.z = acc[i][2] + bi.z; o.w = acc[i][3] + bi.w;
        if (res) {
            float4 rv = *(const float4*)&res[(size_t)r*ldr + c];
            o.x += rv.x; o.y += rv.y; o.z += rv.z; o.w += rv.w;
        }
        if (relu) {
            o.x = fmaxf(o.x, 0.f); o.y = fmaxf(o.y, 0.f);
            o.z = fmaxf(o.z, 0.f); o.w = fmaxf(o.w, 0.f);
        }
        *(float4*)&C[(size_t)r*ldc + c] = o;
    }
}

// ---------------------------------------------------------------------------
// Logits: AW[b,h,i,j] = (Q_h[i,:].K_h[j,:]) * 0.125. Both operands K-contig.
// 128x64 tile / 8x4 micro. Causal: skip tiles with col0 > row0+127 entirely
// (no compute, no write — the causal softmax never reads that region).
// Grid: (T/64, S/128, B*H)
// ---------------------------------------------------------------------------
__global__ __launch_bounds__(256) void logits_kernel(
    const float* __restrict__ Q, const float* __restrict__ Km,
    float* __restrict__ AW, int causal)
{
    const int row0 = blockIdx.y * 128, col0 = blockIdx.x * 64;
    if (causal && col0 > row0 + 127) return;

    const int z = blockIdx.z;
    const int b = z >> 3, h = z & 7;
    const float* Aq = Q  + (size_t)b*SS*DD + h*DKK;
    const float* Bk = Km + (size_t)b*TT*DD + h*DKK;
    float* Cw = AW + (size_t)z*SS*TT;

    __shared__ float As[16][132];
    __shared__ float Bs[16][68];
    const int tid = threadIdx.x;
    const int tx = tid & 15, ty = tid >> 4;

    const int ar = tid >> 1, ak = (tid & 1) * 8;   // Q: 128 rows x 16 k
    const int bn_ = tid >> 2, bk = (tid & 3) * 4;  // K: 64 rows x 16 k

    const float* Aptr = Aq + (size_t)(row0 + ar)*DD + ak;
    const float* Bptr = Bk + (size_t)(col0 + bn_)*DD + bk;

    float4 pa0 = *(const float4*)(Aptr);
    float4 pa1 = *(const float4*)(Aptr + 4);
    float4 pb  = *(const float4*)(Bptr);

    float acc[8][4] = {};
    #pragma unroll
    for (int k0 = 0; k0 < DKK; k0 += 16) {
        As[ak+0][ar]=pa0.x; As[ak+1][ar]=pa0.y; As[ak+2][ar]=pa0.z; As[ak+3][ar]=pa0.w;
        As[ak+4][ar]=pa1.x; As[ak+5][ar]=pa1.y; As[ak+6][ar]=pa1.z; As[ak+7][ar]=pa1.w;
        Bs[bk+0][bn_]=pb.x; Bs[bk+1][bn_]=pb.y; Bs[bk+2][bn_]=pb.z; Bs[bk+3][bn_]=pb.w;
        __syncthreads();
        if (k0 + 16 < DKK) {
            pa0 = *(const float4*)(Aptr + k0 + 16);
            pa1 = *(const float4*)(Aptr + k0 + 20);
            pb  = *(const float4*)(Bptr + k0 + 16);
        }
        #pragma unroll
        for (int kk = 0; kk < 16; kk++) {
            float4 a0 = *(const float4*)&As[kk][ty*8];
            float4 a1 = *(const float4*)&As[kk][ty*8+4];
            float4 b  = *(const float4*)&Bs[kk][tx*4];
            float am[8] = {a0.x,a0.y,a0.z,a0.w,a1.x,a1.y,a1.z,a1.w};
            float bv[4] = {b.x,b.y,b.z,b.w};
            #pragma unroll
            for (int i = 0; i < 8; i++)
                #pragma unroll
                for (int j = 0; j < 4; j++)
                    acc[i][j] += am[i]*bv[j];
        }
        __syncthreads();
    }
    const int c = col0 + tx*4;
    #pragma unroll
    for (int i = 0; i < 8; i++) {
        int r = row0 + ty*8 + i;
        float4 o;
        o.x = acc[i][0]*0.125f; o.y = acc[i][1]*0.125f;
        o.z = acc[i][2]*0.125f; o.w = acc[i][3]*0.125f;
        *(float4*)&Cw[(size_t)r*TT + c] = o;
    }
}

// ---------------------------------------------------------------------------
// Non-causal row softmax in place. One block per row (TT=2048), 256 threads.
// ---------------------------------------------------------------------------
__global__ __launch_bounds__(256) void softmax_kernel(float* __restrict__ AW)
{
    const int tid = threadIdx.x;
    float4* r4 = (float4*)(AW + (size_t)blockIdx.x * TT);
    float4 v0 = r4[tid];
    float4 v1 = r4[tid + 256];

    float m = fmaxf(fmaxf(fmaxf(v0.x,v0.y),fmaxf(v0.z,v0.w)),
                    fmaxf(fmaxf(v1.x,v1.y),fmaxf(v1.z,v1.w)));
    #pragma unroll
    for (int o = 16; o > 0; o >>= 1) m = fmaxf(m, __shfl_xor_sync(0xffffffffu, m, o));
    __shared__ float red[8];
    if ((tid & 31) == 0) red[tid >> 5] = m;
    __syncthreads();
    float bm = red[0];
    #pragma unroll
    for (int i = 1; i < 8; i++) bm = fmaxf(bm, red[i]);
    __syncthreads();

    v0.x = __expf(v0.x - bm); v0.y = __expf(v0.y - bm);
    v0.z = __expf(v0.z - bm); v0.w = __expf(v0.w - bm);
    v1.x = __expf(v1.x - bm); v1.y = __expf(v1.y - bm);
    v1.z = __expf(v1.z - bm); v1.w = __expf(v1.w - bm);
    float s = v0.x+v0.y+v0.z+v0.w + v1.x+v1.y+v1.z+v1.w;
    #pragma unroll
    for (int o = 16; o > 0; o >>= 1) s += __shfl_xor_sync(0xffffffffu, s, o);
    if ((tid & 31) == 0) red[tid >> 5] = s;
    __syncthreads();
    float bs = 0.f;
    #pragma unroll
    for (int i = 0; i < 8; i++) bs += red[i];
    float inv = 1.f / bs;

    v0.x *= inv; v0.y *= inv; v0.z *= inv; v0.w *= inv;
    v1.x *= inv; v1.y *= inv; v1.z *= inv; v1.w *= inv;
    r4[tid] = v0;
    r4[tid + 256] = v1;
}

// ---------------------------------------------------------------------------
// Causal softmax: row i uses only j<=i (masked region is NEVER read — it was
// never written), writes exact 0 for j>i.
// ---------------------------------------------------------------------------
__global__ __launch_bounds__(256) void softmax_causal_kernel(float* __restrict__ AW)
{
    const int tid = threadIdx.x;
    const int i = blockIdx.x & (SS - 1);       // row position in sequence
    float4* r4 = (float4*)(AW + (size_t)blockIdx.x * TT);

    const float NEG = -1e30f;
    int j0 = tid * 4, j1 = (tid + 256) * 4;
    float4 v0 = (j0 <= i) ? r4[tid]       : make_float4(NEG,NEG,NEG,NEG);
    float4 v1 = (j1 <= i) ? r4[tid + 256] : make_float4(NEG,NEG,NEG,NEG);
    if (j0     > i) v0.x = NEG;
    if (j0 + 1 > i) v0.y = NEG;
    if (j0 + 2 > i) v0.z = NEG;
    if (j0 + 3 > i) v0.w = NEG;
    if (j1     > i) v1.x = NEG;
    if (j1 + 1 > i) v1.y = NEG;
    if (j1 + 2 > i) v1.z = NEG;
    if (j1 + 3 > i) v1.w = NEG;

    float m = fmaxf(fmaxf(fmaxf(v0.x,v0.y),fmaxf(v0.z,v0.w)),
                    fmaxf(fmaxf(v1.x,v1.y),fmaxf(v1.z,v1.w)));
    #pragma unroll
    for (int o = 16; o > 0; o >>= 1) m = fmaxf(m, __shfl_xor_sync(0xffffffffu, m, o));
    __shared__ float red[8];
    if ((tid & 31) == 0) red[tid >> 5] = m;
    __syncthreads();
    float bm = red[0];
    #pragma unroll
    for (int k = 1; k < 8; k++) bm = fmaxf(bm, red[k]);
    __syncthreads();

    v0.x = __expf(v0.x - bm); v0.y = __expf(v0.y - bm);
    v0.z = __expf(v0.z - bm); v0.w = __expf(v0.w - bm);
    v1.x = __expf(v1.x - bm); v1.y = __expf(v1.y - bm);
    v1.z = __expf(v1.z - bm); v1.w = __expf(v1.w - bm);
    float s = v0.x+v0.y+v0.z+v0.w + v1.x+v1.y+v1.z+v1.w;
    #pragma unroll
    for (int o = 16; o > 0; o >>= 1) s += __shfl_xor_sync(0xffffffffu, s, o);
    if ((tid & 31) == 0) red[tid >> 5] = s;
    __syncthreads();
    float bs = 0.f;
    #pragma unroll
    for (int k = 0; k < 8; k++) bs += red[k];
    float inv = 1.f / bs;

    v0.x *= inv; v0.y *= inv; v0.z *= inv; v0.w *= inv;
    v1.x *= inv; v1.y *= inv; v1.z *= inv; v1.w *= inv;
    r4[tid] = v0;
    r4[tid + 256] = v1;
}

// ---------------------------------------------------------------------------
// AV: O[b,i,h*64+d] = sum_j AW[b,h,i,j] * V[b,j,h*64+d]
// 128x64 tile / 8x4 micro. Causal: K-loop stops at row0+128 (aw is exact 0
// beyond the diagonal). Grid: (1, S/128, B*H)
// ---------------------------------------------------------------------------
__global__ __launch_bounds__(256) void av_kernel(
    const float* __restrict__ AW, const float* __restrict__ V,
    float* __restrict__ O, int causal)
{
    const int z = blockIdx.z, b = z >> 3, h = z & 7;
    const float* Aa = AW + (size_t)z*SS*TT;
    const float* Bv = V + (size_t)b*TT*DD + h*DKK;
    float* Co = O + (size_t)b*SS*DD + h*DKK;
    const int tid = threadIdx.x;
    const int tx = tid & 15, ty = tid >> 4;
    const int row0 = blockIdx.y * 128, col0 = blockIdx.x * 64;
    const int K = causal ? (row0 + 128) : TT;

    __shared__ float As[16][132];
    __shared__ float Bs[16][68];
    const int ar = tid >> 1, ak = (tid & 1) * 8;
    const int br = tid >> 4, bc = (tid & 15) * 4;

    const float* Aptr = Aa + (size_t)(row0 + ar)*TT + ak;
    const float* Bptr = Bv + (size_t)br*DD + col0 + bc;

    float4 pa0 = *(const float4*)(Aptr);
    float4 pa1 = *(const float4*)(Aptr + 4);
    float4 pb  = *(const float4*)(Bptr);

    float acc[8][4] = {};
    for (int k0 = 0; k0 < K; k0 += 16) {
        As[ak+0][ar]=pa0.x; As[ak+1][ar]=pa0.y; As[ak+2][ar]=pa0.z; As[ak+3][ar]=pa0.w;
        As[ak+4][ar]=pa1.x; As[ak+5][ar]=pa1.y; As[ak+6][ar]=pa1.z; As[ak+7][ar]=pa1.w;
        *(float4*)&Bs[br][bc] = pb;
        __syncthreads();
        if (k0 + 16 < K) {
            pa0 = *(const float4*)(Aptr + k0 + 16);
            pa1 = *(const float4*)(Aptr + k0 + 20);
            pb  = *(const float4*)(Bptr + (size_t)(k0 + 16)*DD);
        }
        #pragma unroll
        for (int kk = 0; kk < 16; kk++) {
            float4 a0 = *(const float4*)&As[kk][ty*8];
            float4 a1 = *(const float4*)&As[kk][ty*8+4];
            float4 b  = *(const float4*)&Bs[kk][tx*4];
            float am[8] = {a0.x,a0.y,a0.z,a0.w,a1.x,a1.y,a1.z,a1.w};
            float bv[4] = {b.x,b.y,b.z,b.w};
            #pragma unroll
            for (int i = 0; i < 8; i++)
                #pragma unroll
                for (int j = 0; j < 4; j++)
                    acc[i][j] += am[i]*bv[j];
        }
        __syncthreads();
    }
    const int c = col0 + tx*4;
    #pragma unroll
    for (int i = 0; i < 8; i++) {
        int r = row0 + ty*8 + i;
        float4 o;
        o.x = acc[i][0]; o.y = acc[i][1]; o.z = acc[i][2]; o.w = acc[i][3];
        *(float4*)&Co[(size_t)r*DD + c] = o;
    }
}

// ---------------------------------------------------------------------------
// LayerNorm over D=512. One block per row, 128 threads (float4 each).
// ---------------------------------------------------------------------------
__global__ __launch_bounds__(128) void ln_kernel(
    const float* __restrict__ X, const float* __restrict__ g,
    const float* __restrict__ be, float* __restrict__ O)
{
    const int tid = threadIdx.x;
    const float4* x4 = (const float4*)(X + (size_t)blockIdx.x * DD);
    float4 xv = x4[tid];
    float s  = xv.x + xv.y + xv.z + xv.w;
    float sq = xv.x*xv.x + xv.y*xv.y + xv.z*xv.z + xv.w*xv.w;
    #pragma unroll
    for (int o = 16; o > 0; o >>= 1) {
        s  += __shfl_xor_sync(0xffffffffu, s,  o);
        sq += __shfl_xor_sync(0xffffffffu, sq, o);
    }
    __shared__ float ss[4], ssq[4];
    if ((tid & 31) == 0) { ss[tid >> 5] = s; ssq[tid >> 5] = sq; }
    __syncthreads();
    s  = ss[0]  + ss[1]  + ss[2]  + ss[3];
    sq = ssq[0] + ssq[1] + ssq[2] + ssq[3];
    const float invD = 1.f / DD;
    float m = s * invD;
    float var = sq * invD - m*m;
    float rstd = rsqrtf(var + 1e-6f);
    float4 gv = ((const float4*)g)[tid];
    float4 bv = ((const float4*)be)[tid];
    float4 o;
    o.x = (xv.x - m)*rstd*gv.x + bv.x;
    o.y = (xv.y - m)*rstd*gv.y + bv.y;
    o.z = (xv.z - m)*rstd*gv.z + bv.z;
    o.w = (xv.w - m)*rstd*gv.w + bv.w;
    ((float4*)(O + (size_t)blockIdx.x * DD))[tid] = o;
}

// ---------------------------------------------------------------------------
// Host side
// ---------------------------------------------------------------------------
static float* scratch_ptr() {
    static float* p = nullptr;
    if (!p) cudaGetSymbolAddress((void**)&p, g_scratch);
    return p;
}

extern "C" void kernel_launch(void* const* d_in, const int* in_sizes, int n_in,
                              void* d_out, int out_size)
{
    const float* x   = (const float*)d_in[0];
    const float* enc = (const float*)d_in[1];
    // d_in[2] = look_ahead_mask (causal; applied analytically)
    const float* wq1 = (const float*)d_in[3];  const float* bq1 = (const float*)d_in[4];
    const float* wk1 = (const float*)d_in[5];  const float* bk1 = (const float*)d_in[6];
    const float* wv1 = (const float*)d_in[7];  const float* bv1 = (const float*)d_in[8];
    const float* wo1 = (const float*)d_in[9];  const float* bo1 = (const float*)d_in[10];
    const float* wq2 = (const float*)d_in[11]; const float* bq2 = (const float*)d_in[12];
    const float* wk2 = (const float*)d_in[13]; const float* bk2 = (const float*)d_in[14];
    const float* wv2 = (const float*)d_in[15]; const float* bv2 = (const float*)d_in[16];
    const float* wo2 = (const float*)d_in[17]; const float* bo2 = (const float*)d_in[18];
    const float* wf1 = (const float*)d_in[19]; const float* bf1 = (const float*)d_in[20];
    const float* wf2 = (const float*)d_in[21]; const float* bf2 = (const float*)d_in[22];
    const float* g1  = (const float*)d_in[23]; const float* be1 = (const float*)d_in[24];
    const float* g2  = (const float*)d_in[25]; const float* be2 = (const float*)d_in[26];
    const float* g3  = (const float*)d_in[27]; const float* be3 = (const float*)d_in[28];

    float* scr  = scratch_ptr();
    float* q    = scr;
    float* k    = q    + NSD;
    float* v    = k    + NSD;
    float* attn = v    + NSD;
    float* ybuf = attn + NSD;
    float* o1   = ybuf + NSD;
    float* o2   = o1   + NSD;
    float* hh   = o2   + NSD;

    float* out3 = (float*)d_out;
    float* aw1  = out3 + NSD;        // [B,H,S,T]
    float* aw2  = aw1  + AW_ELEMS;   // [B,H,S,T]

    dim3 thr(256);
    dim3 gProj(DD/64,  BB*SS/128);        // (8, 32)
    dim3 gLog (TT/64,  SS/128, BB*HH);    // (32, 16, 16)
    dim3 gAv  (1,      SS/128, BB*HH);    // (1, 16, 16)
    dim3 gFf1 (FFF/64, BB*SS/128);        // (32, 32)
    dim3 gFf2 (DD/64,  BB*SS/128);        // (8, 32)

    // ---- self-attention (causal) ----
    sgemm_kernel<<<gProj, thr>>>(x, DD, wq1, DD, q, DD, bq1, nullptr, 0, DD, 0);
    sgemm_kernel<<<gProj, thr>>>(x, DD, wk1, DD, k, DD, bk1, nullptr, 0, DD, 0);
    sgemm_kernel<<<gProj, thr>>>(x, DD, wv1, DD, v, DD, bv1, nullptr, 0, DD, 0);
    logits_kernel<<<gLog, thr>>>(q, k, aw1, 1);
    softmax_causal_kernel<<<BB*HH*SS, 256>>>(aw1);
    av_kernel<<<gAv, thr>>>(aw1, v, attn, 1);
    sgemm_kernel<<<gProj, thr>>>(attn, DD, wo1, DD, ybuf, DD, bo1, x, DD, DD, 0);
    ln_kernel<<<BB*SS, 128>>>(ybuf, g1, be1, o1);

    // ---- cross-attention (no mask) ----
    sgemm_kernel<<<gProj, thr>>>(o1,  DD, wq2, DD, q, DD, bq2, nullptr, 0, DD, 0);
    sgemm_kernel<<<gProj, thr>>>(enc, DD, wk2, DD, k, DD, bk2, nullptr, 0, DD, 0);
    sgemm_kernel<<<gProj, thr>>>(enc, DD, wv2, DD, v, DD, bv2, nullptr, 0, DD, 0);
    logits_kernel<<<gLog, thr>>>(q, k, aw2, 0);
    softmax_kernel<<<BB*HH*SS, 256>>>(aw2);
    av_kernel<<<gAv, thr>>>(aw2, v, attn, 0);
    sgemm_kernel<<<gProj, thr>>>(attn, DD, wo2, DD, ybuf, DD, bo2, o1, DD, DD, 0);
    ln_kernel<<<BB*SS, 128>>>(ybuf, g2, be2, o2);

    // ---- FFN ----
    sgemm_kernel<<<gFf1, thr>>>(o2, DD, wf1, FFF, hh, FFF, bf1, nullptr, 0, DD, 1);
    sgemm_kernel<<<gFf2, thr>>>(hh, FFF, wf2, DD, ybuf, DD, bf2, o2, DD, FFF, 0);
    ln_kernel<<<BB*SS, 128>>>(ybuf, g3, be3, out3);
}

// round 6
// speedup vs baseline: 1.8681x; 1.4072x over previous
#include <cuda_runtime.h>
#include <cstdint>
#include <cstddef>

// Problem dims (fixed)
#define BB   2
#define SS   2048
#define TT   2048
#define DD   512
#define HH   8
#define DKK  64
#define FFF  2048

#define NSD  (BB*SS*DD)
#define NSF  (BB*SS*FFF)
#define AW_ELEMS ((size_t)BB*HH*(size_t)SS*TT)
#define WT_ELEMS (8*DD*DD + DD*FFF + FFF*DD)

// q,k,v,attn,ybuf,o1,o2 (7*NSD) + hh (NSF) + vt (NSD) + transposed weights
__device__ float g_scratch[7*NSD + NSF + NSD + WT_ELEMS];

// ===========================================================================
// tf32 helpers (sm_80+ PTX — legal on plain sm_103 target)
// ===========================================================================
__device__ __forceinline__ void cvt4_tf32(uint32_t* t, float4 v){
  asm("cvt.rna.tf32.f32 %0, %1;":"=r"(t[0]):"f"(v.x));
  asm("cvt.rna.tf32.f32 %0, %1;":"=r"(t[1]):"f"(v.y));
  asm("cvt.rna.tf32.f32 %0, %1;":"=r"(t[2]):"f"(v.z));
  asm("cvt.rna.tf32.f32 %0, %1;":"=r"(t[3]):"f"(v.w));
}
__device__ __forceinline__ void mma_tf32(float* d, const uint32_t* a, const uint32_t* b){
  asm volatile(
    "mma.sync.aligned.m16n8k8.row.col.f32.tf32.tf32.f32 "
    "{%0,%1,%2,%3}, {%4,%5,%6,%7}, {%8,%9}, {%0,%1,%2,%3};"
    : "+f"(d[0]), "+f"(d[1]), "+f"(d[2]), "+f"(d[3])
    : "r"(a[0]), "r"(a[1]), "r"(a[2]), "r"(a[3]), "r"(b[0]), "r"(b[1]));
}

// ===========================================================================
// Warp-MMA tf32 GEMM: C[M,N] = scale*(A[M,K] @ Bt[N,K]^T) (+bias)(+res)(relu)
// Block tile 128x64, 8 warps (4m x 2n), warp tile 32x32, mma m16n8k8, BK=16,
// double-buffered smem (stride 20 words -> conflict-free fragment reads).
// A-fragment register order per PTX ISA: a0=(g,t4) a1=(g+8,t4) a2=(g,t4+4)
// a3=(g+8,t4+4).  B-fragment: b0=(k=t4,n=g) b1=(k=t4+4,n=g).
// causal: 0 none; 1 skip tiles fully above diagonal; 2 limit K to row0+128.
// Grid (N/64, M/128, Z); z -> (zb=z>>3, zh=z&7) offsets via strides.
// ===========================================================================
#define ASTRIDE 20

__global__ __launch_bounds__(256) void tc_gemm(
    const float* __restrict__ A, long long sab, long long sah, int lda,
    const float* __restrict__ Bt, long long sbb, long long sbh, int ldb,
    float* __restrict__ C, long long scb, long long sch, int ldc,
    const float* __restrict__ bias,
    const float* __restrict__ res, int ldr,
    int K, float scale, int relu, int causal)
{
    const int row0 = blockIdx.y*128, col0 = blockIdx.x*64;
    if (causal==1 && col0 > row0+127) return;
    const int Keff = (causal==2) ? (row0+128) : K;

    const int z = blockIdx.z, zb = z>>3, zh = z&7;
    A  += (size_t)zb*sab + (size_t)zh*sah;
    Bt += (size_t)zb*sbb + (size_t)zh*sbh;
    C  += (size_t)zb*scb + (size_t)zh*sch;

    __shared__ uint32_t As[2][128*ASTRIDE];
    __shared__ uint32_t Bs[2][64*ASTRIDE];

    const int tid = threadIdx.x;
    const int wid = tid>>5, lane = tid&31;
    const int warp_m = wid>>1, warp_n = wid&1;
    const int g = lane>>2, t4 = lane&3;

    // gmem -> smem mapping
    const int ar = tid>>1, ak = (tid&1)*8;   // A: 128 rows x 16 k
    const int br = tid>>2, bk = (tid&3)*4;   // B: 64 rows x 16 k

    const float* Aptr = A + (size_t)(row0+ar)*lda + ak;
    const float* Bptr = Bt + (size_t)(col0+br)*ldb + bk;

    float4 pa0 = *(const float4*)(Aptr);
    float4 pa1 = *(const float4*)(Aptr + 4);
    float4 pb  = *(const float4*)(Bptr);

    float acc[2][4][4] = {};
    const int nIter = Keff >> 4;

    for (int i = 0; i < nIter; i++){
        const int s = i & 1;
        { uint32_t t[4];
          cvt4_tf32(t, pa0); *(uint4*)&As[s][ar*ASTRIDE + ak]     = *(uint4*)t;
          cvt4_tf32(t, pa1); *(uint4*)&As[s][ar*ASTRIDE + ak + 4] = *(uint4*)t;
          cvt4_tf32(t, pb);  *(uint4*)&Bs[s][br*ASTRIDE + bk]     = *(uint4*)t; }
        __syncthreads();
        if (i + 1 < nIter){
            const int kn = (i + 1) << 4;
            pa0 = *(const float4*)(Aptr + kn);
            pa1 = *(const float4*)(Aptr + kn + 4);
            pb  = *(const float4*)(Bptr + kn);
        }
        #pragma unroll
        for (int ks = 0; ks < 2; ks++){
            const int kb = ks*8;
            uint32_t af[2][4], bf[4][2];
            #pragma unroll
            for (int mt = 0; mt < 2; mt++){
                const int rA = (warp_m*32 + mt*16 + g)*ASTRIDE + kb + t4;
                af[mt][0] = As[s][rA];                      // (g,     t4)
                af[mt][1] = As[s][rA + 8*ASTRIDE];          // (g+8,   t4)
                af[mt][2] = As[s][rA + 4];                  // (g,   t4+4)
                af[mt][3] = As[s][rA + 8*ASTRIDE + 4];      // (g+8, t4+4)
            }
            #pragma unroll
            for (int nt = 0; nt < 4; nt++){
                const int rB = (warp_n*32 + nt*8 + g)*ASTRIDE + kb + t4;
                bf[nt][0] = Bs[s][rB];                      // (k=t4,   n=g)
                bf[nt][1] = Bs[s][rB + 4];                  // (k=t4+4, n=g)
            }
            #pragma unroll
            for (int mt = 0; mt < 2; mt++)
                #pragma unroll
                for (int nt = 0; nt < 4; nt++)
                    mma_tf32(acc[mt][nt], af[mt], bf[nt]);
        }
        __syncthreads();
    }

    // Epilogue. c0=(g,2t4) c1=(g,2t4+1) c2=(g+8,2t4) c3=(g+8,2t4+1).
    #pragma unroll
    for (int mt = 0; mt < 2; mt++){
        #pragma unroll
        for (int half = 0; half < 2; half++){
            const int r = row0 + warp_m*32 + mt*16 + g + half*8;
            #pragma unroll
            for (int nt = 0; nt < 4; nt++){
                const int c = col0 + warp_n*32 + nt*8 + 2*t4;
                float vx = acc[mt][nt][half*2 + 0] * scale;
                float vy = acc[mt][nt][half*2 + 1] * scale;
                if (bias){ vx += bias[c]; vy += bias[c+1]; }
                if (res){ const float* rp = &res[(size_t)r*ldr + c];
                          vx += rp[0]; vy += rp[1]; }
                if (relu){ vx = fmaxf(vx, 0.f); vy = fmaxf(vy, 0.f); }
                float2 o; o.x = vx; o.y = vy;
                *(float2*)&C[(size_t)r*ldc + c] = o;
            }
        }
    }
}

// ---------------------------------------------------------------------------
// Transpose: in[R,C] -> out[C,R], 32x32 smem tiles. Grid (C/32, R/32, batch).
// ---------------------------------------------------------------------------
__global__ __launch_bounds__(256) void transpose_kernel(
    const float* __restrict__ in, float* __restrict__ out, int R, int C)
{
    __shared__ float t[32][33];
    const float* I = in  + (size_t)blockIdx.z * R * C;
    float*       O = out + (size_t)blockIdx.z * R * C;
    int c0 = blockIdx.x*32, r0 = blockIdx.y*32;
    for (int i = threadIdx.y; i < 32; i += 8)
        t[i][threadIdx.x] = I[(size_t)(r0+i)*C + c0 + threadIdx.x];
    __syncthreads();
    for (int i = threadIdx.y; i < 32; i += 8)
        O[(size_t)(c0+i)*R + r0 + threadIdx.x] = t[threadIdx.x][i];
}

// ---------------------------------------------------------------------------
// Non-causal row softmax in place (row length TT), 256 threads.
// ---------------------------------------------------------------------------
__global__ __launch_bounds__(256) void softmax_kernel(float* __restrict__ AW)
{
    const int tid = threadIdx.x;
    float4* r4 = (float4*)(AW + (size_t)blockIdx.x * TT);
    float4 v0 = r4[tid];
    float4 v1 = r4[tid + 256];

    float m = fmaxf(fmaxf(fmaxf(v0.x,v0.y),fmaxf(v0.z,v0.w)),
                    fmaxf(fmaxf(v1.x,v1.y),fmaxf(v1.z,v1.w)));
    #pragma unroll
    for (int o = 16; o > 0; o >>= 1) m = fmaxf(m, __shfl_xor_sync(0xffffffffu, m, o));
    __shared__ float red[8];
    if ((tid & 31) == 0) red[tid >> 5] = m;
    __syncthreads();
    float bm = red[0];
    #pragma unroll
    for (int i = 1; i < 8; i++) bm = fmaxf(bm, red[i]);
    __syncthreads();

    v0.x = __expf(v0.x - bm); v0.y = __expf(v0.y - bm);
    v0.z = __expf(v0.z - bm); v0.w = __expf(v0.w - bm);
    v1.x = __expf(v1.x - bm); v1.y = __expf(v1.y - bm);
    v1.z = __expf(v1.z - bm); v1.w = __expf(v1.w - bm);
    float s = v0.x+v0.y+v0.z+v0.w + v1.x+v1.y+v1.z+v1.w;
    #pragma unroll
    for (int o = 16; o > 0; o >>= 1) s += __shfl_xor_sync(0xffffffffu, s, o);
    if ((tid & 31) == 0) red[tid >> 5] = s;
    __syncthreads();
    float bs = 0.f;
    #pragma unroll
    for (int i = 0; i < 8; i++) bs += red[i];
    float inv = 1.f / bs;

    v0.x *= inv; v0.y *= inv; v0.z *= inv; v0.w *= inv;
    v1.x *= inv; v1.y *= inv; v1.z *= inv; v1.w *= inv;
    r4[tid] = v0;
    r4[tid + 256] = v1;
}

// ---------------------------------------------------------------------------
// Causal softmax: row i uses only j<=i (masked region never read/written by
// logits), writes exact 0 for j>i.
// ---------------------------------------------------------------------------
__global__ __launch_bounds__(256) void softmax_causal_kernel(float* __restrict__ AW)
{
    const int tid = threadIdx.x;
    const int i = blockIdx.x & (SS - 1);
    float4* r4 = (float4*)(AW + (size_t)blockIdx.x * TT);

    const float NEG = -1e30f;
    int j0 = tid * 4, j1 = (tid + 256) * 4;
    float4 v0 = (j0 <= i) ? r4[tid]       : make_float4(NEG,NEG,NEG,NEG);
    float4 v1 = (j1 <= i) ? r4[tid + 256] : make_float4(NEG,NEG,NEG,NEG);
    if (j0     > i) v0.x = NEG;
    if (j0 + 1 > i) v0.y = NEG;
    if (j0 + 2 > i) v0.z = NEG;
    if (j0 + 3 > i) v0.w = NEG;
    if (j1     > i) v1.x = NEG;
    if (j1 + 1 > i) v1.y = NEG;
    if (j1 + 2 > i) v1.z = NEG;
    if (j1 + 3 > i) v1.w = NEG;

    float m = fmaxf(fmaxf(fmaxf(v0.x,v0.y),fmaxf(v0.z,v0.w)),
                    fmaxf(fmaxf(v1.x,v1.y),fmaxf(v1.z,v1.w)));
    #pragma unroll
    for (int o = 16; o > 0; o >>= 1) m = fmaxf(m, __shfl_xor_sync(0xffffffffu, m, o));
    __shared__ float red[8];
    if ((tid & 31) == 0) red[tid >> 5] = m;
    __syncthreads();
    float bm = red[0];
    #pragma unroll
    for (int kk = 1; kk < 8; kk++) bm = fmaxf(bm, red[kk]);
    __syncthreads();

    v0.x = __expf(v0.x - bm); v0.y = __expf(v0.y - bm);
    v0.z = __expf(v0.z - bm); v0.w = __expf(v0.w - bm);
    v1.x = __expf(v1.x - bm); v1.y = __expf(v1.y - bm);
    v1.z = __expf(v1.z - bm); v1.w = __expf(v1.w - bm);
    float s = v0.x+v0.y+v0.z+v0.w + v1.x+v1.y+v1.z+v1.w;
    #pragma unroll
    for (int o = 16; o > 0; o >>= 1) s += __shfl_xor_sync(0xffffffffu, s, o);
    if ((tid & 31) == 0) red[tid >> 5] = s;
    __syncthreads();
    float bs = 0.f;
    #pragma unroll
    for (int kk = 0; kk < 8; kk++) bs += red[kk];
    float inv = 1.f / bs;

    v0.x *= inv; v0.y *= inv; v0.z *= inv; v0.w *= inv;
    v1.x *= inv; v1.y *= inv; v1.z *= inv; v1.w *= inv;
    r4[tid] = v0;
    r4[tid + 256] = v1;
}

// ---------------------------------------------------------------------------
// LayerNorm over D=512. One block per row, 128 threads.
// ---------------------------------------------------------------------------
__global__ __launch_bounds__(128) void ln_kernel(
    const float* __restrict__ X, const float* __restrict__ g,
    const float* __restrict__ be, float* __restrict__ O)
{
    const int tid = threadIdx.x;
    const float4* x4 = (const float4*)(X + (size_t)blockIdx.x * DD);
    float4 xv = x4[tid];
    float s  = xv.x + xv.y + xv.z + xv.w;
    float sq = xv.x*xv.x + xv.y*xv.y + xv.z*xv.z + xv.w*xv.w;
    #pragma unroll
    for (int o = 16; o > 0; o >>= 1) {
        s  += __shfl_xor_sync(0xffffffffu, s,  o);
        sq += __shfl_xor_sync(0xffffffffu, sq, o);
    }
    __shared__ float ss[4], ssq[4];
    if ((tid & 31) == 0) { ss[tid >> 5] = s; ssq[tid >> 5] = sq; }
    __syncthreads();
    s  = ss[0]  + ss[1]  + ss[2]  + ss[3];
    sq = ssq[0] + ssq[1] + ssq[2] + ssq[3];
    const float invD = 1.f / DD;
    float m = s * invD;
    float var = sq * invD - m*m;
    float rstd = rsqrtf(var + 1e-6f);
    float4 gv = ((const float4*)g)[tid];
    float4 bv = ((const float4*)be)[tid];
    float4 o;
    o.x = (xv.x - m)*rstd*gv.x + bv.x;
    o.y = (xv.y - m)*rstd*gv.y + bv.y;
    o.z = (xv.z - m)*rstd*gv.z + bv.z;
    o.w = (xv.w - m)*rstd*gv.w + bv.w;
    ((float4*)(O + (size_t)blockIdx.x * DD))[tid] = o;
}

// ===========================================================================
// Host side
// ===========================================================================
static float* scratch_ptr() {
    static float* p = nullptr;
    if (!p) cudaGetSymbolAddress((void**)&p, g_scratch);
    return p;
}

extern "C" void kernel_launch(void* const* d_in, const int* in_sizes, int n_in,
                              void* d_out, int out_size)
{
    const float* x   = (const float*)d_in[0];
    const float* enc = (const float*)d_in[1];
    const float* wq1 = (const float*)d_in[3];  const float* bq1 = (const float*)d_in[4];
    const float* wk1 = (const float*)d_in[5];  const float* bk1 = (const float*)d_in[6];
    const float* wv1 = (const float*)d_in[7];  const float* bv1 = (const float*)d_in[8];
    const float* wo1 = (const float*)d_in[9];  const float* bo1 = (const float*)d_in[10];
    const float* wq2 = (const float*)d_in[11]; const float* bq2 = (const float*)d_in[12];
    const float* wk2 = (const float*)d_in[13]; const float* bk2 = (const float*)d_in[14];
    const float* wv2 = (const float*)d_in[15]; const float* bv2 = (const float*)d_in[16];
    const float* wo2 = (const float*)d_in[17]; const float* bo2 = (const float*)d_in[18];
    const float* wf1 = (const float*)d_in[19]; const float* bf1 = (const float*)d_in[20];
    const float* wf2 = (const float*)d_in[21]; const float* bf2 = (const float*)d_in[22];
    const float* g1  = (const float*)d_in[23]; const float* be1 = (const float*)d_in[24];
    const float* g2  = (const float*)d_in[25]; const float* be2 = (const float*)d_in[26];
    const float* g3  = (const float*)d_in[27]; const float* be3 = (const float*)d_in[28];

    float* scr  = scratch_ptr();
    float* q    = scr;
    float* k    = q    + NSD;
    float* v    = k    + NSD;
    float* attn = v    + NSD;
    float* ybuf = attn + NSD;
    float* o1   = ybuf + NSD;
    float* o2   = o1   + NSD;
    float* hh   = o2   + NSD;
    float* vt   = hh   + NSF;
    float* wT   = vt   + NSD;
    float* wq1T = wT;
    float* wk1T = wq1T + DD*DD;
    float* wv1T = wk1T + DD*DD;
    float* wo1T = wv1T + DD*DD;
    float* wq2T = wo1T + DD*DD;
    float* wk2T = wq2T + DD*DD;
    float* wv2T = wk2T + DD*DD;
    float* wo2T = wv2T + DD*DD;
    float* wf1T = wo2T + DD*DD;          // [FFF, DD]
    float* wf2T = wf1T + DD*FFF;         // [DD, FFF]

    float* out3 = (float*)d_out;
    float* aw1  = out3 + NSD;
    float* aw2  = aw1  + AW_ELEMS;

    const int M  = BB*SS;                // 4096
    const long long SD = (long long)SS*DD, ST = (long long)SS*TT;

    dim3 tb(32,8);
    // weight transposes ([K,N] -> [N,K])
    transpose_kernel<<<dim3(16,16,1), tb>>>(wq1, wq1T, DD, DD);
    transpose_kernel<<<dim3(16,16,1), tb>>>(wk1, wk1T, DD, DD);
    transpose_kernel<<<dim3(16,16,1), tb>>>(wv1, wv1T, DD, DD);
    transpose_kernel<<<dim3(16,16,1), tb>>>(wo1, wo1T, DD, DD);
    transpose_kernel<<<dim3(16,16,1), tb>>>(wq2, wq2T, DD, DD);
    transpose_kernel<<<dim3(16,16,1), tb>>>(wk2, wk2T, DD, DD);
    transpose_kernel<<<dim3(16,16,1), tb>>>(wv2, wv2T, DD, DD);
    transpose_kernel<<<dim3(16,16,1), tb>>>(wo2, wo2T, DD, DD);
    transpose_kernel<<<dim3(64,16,1), tb>>>(wf1, wf1T, DD, FFF);
    transpose_kernel<<<dim3(16,64,1), tb>>>(wf2, wf2T, FFF, DD);

    #define GEMM(A_,sab,sah,lda, B_,sbb,sbh,ldb, C_,scb,sch,ldc, bias_,res_,ldr, Mv,Nv,Kv,Zv, sc,rl,cz) \
        tc_gemm<<<dim3((Nv)/64,(Mv)/128,(Zv)), 256>>>( \
            A_,sab,sah,lda, B_,sbb,sbh,ldb, C_,scb,sch,ldc, bias_,res_,ldr, Kv,sc,rl,cz)

    // ---- self-attention (causal) ----
    GEMM(x,0,0,DD,  wq1T,0,0,DD,  q,0,0,DD,  bq1,(const float*)nullptr,0, M,DD,DD,1, 1.f,0,0);
    GEMM(x,0,0,DD,  wk1T,0,0,DD,  k,0,0,DD,  bk1,(const float*)nullptr,0, M,DD,DD,1, 1.f,0,0);
    GEMM(x,0,0,DD,  wv1T,0,0,DD,  v,0,0,DD,  bv1,(const float*)nullptr,0, M,DD,DD,1, 1.f,0,0);
    transpose_kernel<<<dim3(16,64,BB), tb>>>(v, vt, SS, DD);       // vt[b][d][s]
    GEMM(q,SD,64,DD,  k,SD,64,DD,  aw1,8*ST,ST,TT,
         (const float*)nullptr,(const float*)nullptr,0, SS,TT,DKK,BB*HH, 0.125f,0,1);
    softmax_causal_kernel<<<BB*HH*SS, 256>>>(aw1);
    GEMM(aw1,8*ST,ST,TT,  vt,(long long)DD*SS,(long long)64*SS,SS,  attn,SD,64,DD,
         (const float*)nullptr,(const float*)nullptr,0, SS,DKK,TT,BB*HH, 1.f,0,2);
    GEMM(attn,0,0,DD,  wo1T,0,0,DD,  ybuf,0,0,DD,  bo1,x,DD, M,DD,DD,1, 1.f,0,0);
    ln_kernel<<<BB*SS, 128>>>(ybuf, g1, be1, o1);

    // ---- cross-attention (no mask) ----
    GEMM(o1,0,0,DD,   wq2T,0,0,DD,  q,0,0,DD,  bq2,(const float*)nullptr,0, M,DD,DD,1, 1.f,0,0);
    GEMM(enc,0,0,DD,  wk2T,0,0,DD,  k,0,0,DD,  bk2,(const float*)nullptr,0, M,DD,DD,1, 1.f,0,0);
    GEMM(enc,0,0,DD,  wv2T,0,0,DD,  v,0,0,DD,  bv2,(const float*)nullptr,0, M,DD,DD,1, 1.f,0,0);
    transpose_kernel<<<dim3(16,64,BB), tb>>>(v, vt, SS, DD);
    GEMM(q,SD,64,DD,  k,SD,64,DD,  aw2,8*ST,ST,TT,
         (const float*)nullptr,(const float*)nullptr,0, SS,TT,DKK,BB*HH, 0.125f,0,0);
    softmax_kernel<<<BB*HH*SS, 256>>>(aw2);
    GEMM(aw2,8*ST,ST,TT,  vt,(long long)DD*SS,(long long)64*SS,SS,  attn,SD,64,DD,
         (const float*)nullptr,(const float*)nullptr,0, SS,DKK,TT,BB*HH, 1.f,0,0);
    GEMM(attn,0,0,DD,  wo2T,0,0,DD,  ybuf,0,0,DD,  bo2,o1,DD, M,DD,DD,1, 1.f,0,0);
    ln_kernel<<<BB*SS, 128>>>(ybuf, g2, be2, o2);

    // ---- FFN ----
    GEMM(o2,0,0,DD,   wf1T,0,0,DD,   hh,0,0,FFF,  bf1,(const float*)nullptr,0, M,FFF,DD,1,  1.f,1,0);
    GEMM(hh,0,0,FFF,  wf2T,0,0,FFF,  ybuf,0,0,DD, bf2,o2,DD,                   M,DD,FFF,1,  1.f,0,0);
    ln_kernel<<<BB*SS, 128>>>(ybuf, g3, be3, out3);
}

// round 9
// speedup vs baseline: 2.1393x; 1.1452x over previous
#include <cuda_runtime.h>
#include <cstdint>
#include <cstddef>

// Problem dims (fixed)
#define BB   2
#define SS   2048
#define TT   2048
#define DD   512
#define HH   8
#define DKK  64
#define FFF  2048

#define NSD  (BB*SS*DD)
#define NSF  (BB*SS*FFF)
#define AW_ELEMS ((size_t)BB*HH*(size_t)SS*TT)

// q,k,v,attn,ybuf,o1,o2 (7*NSD) + hh (NSF)
__device__ float g_scratch[7*NSD + NSF];

// ===========================================================================
// tf32 helpers (sm_80+ PTX — legal on plain sm_103 target)
// ===========================================================================
__device__ __forceinline__ void cvt4_tf32(uint32_t* t, float4 v){
  asm("cvt.rna.tf32.f32 %0, %1;":"=r"(t[0]):"f"(v.x));
  asm("cvt.rna.tf32.f32 %0, %1;":"=r"(t[1]):"f"(v.y));
  asm("cvt.rna.tf32.f32 %0, %1;":"=r"(t[2]):"f"(v.z));
  asm("cvt.rna.tf32.f32 %0, %1;":"=r"(t[3]):"f"(v.w));
}
__device__ __forceinline__ void mma_tf32(float* d, const uint32_t* a, const uint32_t* b){
  asm volatile(
    "mma.sync.aligned.m16n8k8.row.col.f32.tf32.tf32.f32 "
    "{%0,%1,%2,%3}, {%4,%5,%6,%7}, {%8,%9}, {%0,%1,%2,%3};"
    : "+f"(d[0]), "+f"(d[1]), "+f"(d[2]), "+f"(d[3])
    : "r"(a[0]), "r"(a[1]), "r"(a[2]), "r"(a[3]), "r"(b[0]), "r"(b[1]));
}

// ===========================================================================
// Warp-MMA tf32 GEMM (R6-proven core): C = scale*(A[M,K] @ B^T) (+bias)(+res)(relu)
// Block tile 128x64, 8 warps (4m x 2n), warp tile 32x32, mma m16n8k8, BK=16,
// double-buffered smem, register prefetch, cvt.rna.tf32 on the smem-store path.
// BL=0: B given as [N,K] row-major (smem [n][k], stride 20).
// BL=1: B given as [K,N] row-major (smem [k][n], stride 72) — no transposes.
// A-fragment order (PTX ISA): a0=(g,t4) a1=(g+8,t4) a2=(g,t4+4) a3=(g+8,t4+4).
// causal: 0 none; 1 skip tiles fully above diagonal; 2 limit K to row0+128.
// Grid (N/64, M/128, Z); z -> (zb=z>>3, zh=z&7) offsets via strides.
// ===========================================================================
#define ASTRIDE 20
#define BSTRIDE1 72

template<int BL>
__global__ __launch_bounds__(256) void tc_gemm(
    const float* __restrict__ A, long long sab, long long sah, int lda,
    const float* __restrict__ Bt, long long sbb, long long sbh, int ldb,
    float* __restrict__ C, long long scb, long long sch, int ldc,
    const float* __restrict__ bias,
    const float* __restrict__ res, int ldr,
    int K, float scale, int relu, int causal)
{
    const int row0 = blockIdx.y*128, col0 = blockIdx.x*64;
    if (causal==1 && col0 > row0+127) return;
    const int Keff = (causal==2) ? (row0+128) : K;

    const int z = blockIdx.z, zb = z>>3, zh = z&7;
    A  += (size_t)zb*sab + (size_t)zh*sah;
    Bt += (size_t)zb*sbb + (size_t)zh*sbh;
    C  += (size_t)zb*scb + (size_t)zh*sch;

    __shared__ uint32_t As[2][128*ASTRIDE];
    __shared__ uint32_t Bs[2][64*ASTRIDE];   // layout1 uses 16*72=1152 <= 1280 words

    const int tid = threadIdx.x;
    const int wid = tid>>5, lane = tid&31;
    const int warp_m = wid>>1, warp_n = wid&1;
    const int g = lane>>2, t4 = lane&3;

    // gmem -> smem mapping
    const int ar = tid>>1, ak = (tid&1)*8;   // A: 128 rows x 16 k
    const int br0 = tid>>2, bk0 = (tid&3)*4; // B layout0: 64 n-rows x 16 k
    const int br1 = tid>>4, bn1 = (tid&15)*4;// B layout1: 16 k-rows x 64 n

    const float* Aptr = A + (size_t)(row0+ar)*lda + ak;
    const float* Bptr = (BL==0)
        ? Bt + (size_t)(col0+br0)*ldb + bk0
        : Bt + (size_t)br1*ldb + col0 + bn1;

    float4 pa0 = *(const float4*)(Aptr);
    float4 pa1 = *(const float4*)(Aptr + 4);
    float4 pb  = *(const float4*)(Bptr);

    float acc[2][4][4] = {};
    const int nIter = Keff >> 4;

    for (int i = 0; i < nIter; i++){
        const int s = i & 1;
        const int k0 = i << 4;
        { uint32_t t[4];
          cvt4_tf32(t, pa0); *(uint4*)&As[s][ar*ASTRIDE + ak]     = *(uint4*)t;
          cvt4_tf32(t, pa1); *(uint4*)&As[s][ar*ASTRIDE + ak + 4] = *(uint4*)t;
          if (BL == 0){
            cvt4_tf32(t, pb); *(uint4*)&Bs[s][br0*ASTRIDE + bk0] = *(uint4*)t;
          } else {
            cvt4_tf32(t, pb); *(uint4*)&Bs[s][br1*BSTRIDE1 + bn1] = *(uint4*)t;
          }
        }
        __syncthreads();
        if (i + 1 < nIter){
            pa0 = *(const float4*)(Aptr + k0 + 16);
            pa1 = *(const float4*)(Aptr + k0 + 20);
            pb  = (BL==0) ? *(const float4*)(Bptr + k0 + 16)
                          : *(const float4*)(Bptr + (size_t)(k0 + 16)*ldb);
        }
        #pragma unroll
        for (int ks = 0; ks < 2; ks++){
            const int kb = ks*8;
            uint32_t af[2][4], bf[4][2];
            #pragma unroll
            for (int mt = 0; mt < 2; mt++){
                const int rA = (warp_m*32 + mt*16 + g)*ASTRIDE + kb + t4;
                af[mt][0] = As[s][rA];                      // (g,     t4)
                af[mt][1] = As[s][rA + 8*ASTRIDE];          // (g+8,   t4)
                af[mt][2] = As[s][rA + 4];                  // (g,   t4+4)
                af[mt][3] = As[s][rA + 8*ASTRIDE + 4];      // (g+8, t4+4)
            }
            if (BL == 0){
                #pragma unroll
                for (int nt = 0; nt < 4; nt++){
                    const int rB = (warp_n*32 + nt*8 + g)*ASTRIDE + kb + t4;
                    bf[nt][0] = Bs[s][rB];                  // (k=t4,   n=g)
                    bf[nt][1] = Bs[s][rB + 4];              // (k=t4+4, n=g)
                }
            } else {
                #pragma unroll
                for (int nt = 0; nt < 4; nt++){
                    const int cB = warp_n*32 + nt*8 + g;
                    bf[nt][0] = Bs[s][(kb + t4)*BSTRIDE1 + cB];
                    bf[nt][1] = Bs[s][(kb + t4 + 4)*BSTRIDE1 + cB];
                }
            }
            #pragma unroll
            for (int mt = 0; mt < 2; mt++)
                #pragma unroll
                for (int nt = 0; nt < 4; nt++)
                    mma_tf32(acc[mt][nt], af[mt], bf[nt]);
        }
        __syncthreads();
    }

    // Epilogue. c0=(g,2t4) c1=(g,2t4+1) c2=(g+8,2t4) c3=(g+8,2t4+1).
    #pragma unroll
    for (int mt = 0; mt < 2; mt++){
        #pragma unroll
        for (int half = 0; half < 2; half++){
            const int r = row0 + warp_m*32 + mt*16 + g + half*8;
            #pragma unroll
            for (int nt = 0; nt < 4; nt++){
                const int c = col0 + warp_n*32 + nt*8 + 2*t4;
                float vx = acc[mt][nt][half*2 + 0] * scale;
                float vy = acc[mt][nt][half*2 + 1] * scale;
                if (bias){ vx += bias[c]; vy += bias[c+1]; }
                if (res){ const float* rp = &res[(size_t)r*ldr + c];
                          vx += rp[0]; vy += rp[1]; }
                if (relu){ vx = fmaxf(vx, 0.f); vy = fmaxf(vy, 0.f); }
                float2 o; o.x = vx; o.y = vy;
                *(float2*)&C[(size_t)r*ldc + c] = o;
            }
        }
    }
}

// ---------------------------------------------------------------------------
// Non-causal row softmax in place (row length TT), 256 threads.
// ---------------------------------------------------------------------------
__global__ __launch_bounds__(256) void softmax_kernel(float* __restrict__ AW)
{
    const int tid = threadIdx.x;
    float4* r4 = (float4*)(AW + (size_t)blockIdx.x * TT);
    float4 v0 = r4[tid];
    float4 v1 = r4[tid + 256];

    float m = fmaxf(fmaxf(fmaxf(v0.x,v0.y),fmaxf(v0.z,v0.w)),
                    fmaxf(fmaxf(v1.x,v1.y),fmaxf(v1.z,v1.w)));
    #pragma unroll
    for (int o = 16; o > 0; o >>= 1) m = fmaxf(m, __shfl_xor_sync(0xffffffffu, m, o));
    __shared__ float red[8];
    if ((tid & 31) == 0) red[tid >> 5] = m;
    __syncthreads();
    float bm = red[0];
    #pragma unroll
    for (int i = 1; i < 8; i++) bm = fmaxf(bm, red[i]);
    __syncthreads();

    v0.x = __expf(v0.x - bm); v0.y = __expf(v0.y - bm);
    v0.z = __expf(v0.z - bm); v0.w = __expf(v0.w - bm);
    v1.x = __expf(v1.x - bm); v1.y = __expf(v1.y - bm);
    v1.z = __expf(v1.z - bm); v1.w = __expf(v1.w - bm);
    float s = v0.x+v0.y+v0.z+v0.w + v1.x+v1.y+v1.z+v1.w;
    #pragma unroll
    for (int o = 16; o > 0; o >>= 1) s += __shfl_xor_sync(0xffffffffu, s, o);
    if ((tid & 31) == 0) red[tid >> 5] = s;
    __syncthreads();
    float bs = 0.f;
    #pragma unroll
    for (int i = 0; i < 8; i++) bs += red[i];
    float inv = 1.f / bs;

    v0.x *= inv; v0.y *= inv; v0.z *= inv; v0.w *= inv;
    v1.x *= inv; v1.y *= inv; v1.z *= inv; v1.w *= inv;
    r4[tid] = v0;
    r4[tid + 256] = v1;
}

// ---------------------------------------------------------------------------
// Causal softmax: row i uses only j<=i (masked region never read/written by
// logits), writes exact 0 for j>i.
// ---------------------------------------------------------------------------
__global__ __launch_bounds__(256) void softmax_causal_kernel(float* __restrict__ AW)
{
    const int tid = threadIdx.x;
    const int i = blockIdx.x & (SS - 1);
    float4* r4 = (float4*)(AW + (size_t)blockIdx.x * TT);

    const float NEG = -1e30f;
    int j0 = tid * 4, j1 = (tid + 256) * 4;
    float4 v0 = (j0 <= i) ? r4[tid]       : make_float4(NEG,NEG,NEG,NEG);
    float4 v1 = (j1 <= i) ? r4[tid + 256] : make_float4(NEG,NEG,NEG,NEG);
    if (j0     > i) v0.x = NEG;
    if (j0 + 1 > i) v0.y = NEG;
    if (j0 + 2 > i) v0.z = NEG;
    if (j0 + 3 > i) v0.w = NEG;
    if (j1     > i) v1.x = NEG;
    if (j1 + 1 > i) v1.y = NEG;
    if (j1 + 2 > i) v1.z = NEG;
    if (j1 + 3 > i) v1.w = NEG;

    float m = fmaxf(fmaxf(fmaxf(v0.x,v0.y),fmaxf(v0.z,v0.w)),
                    fmaxf(fmaxf(v1.x,v1.y),fmaxf(v1.z,v1.w)));
    #pragma unroll
    for (int o = 16; o > 0; o >>= 1) m = fmaxf(m, __shfl_xor_sync(0xffffffffu, m, o));
    __shared__ float red[8];
    if ((tid & 31) == 0) red[tid >> 5] = m;
    __syncthreads();
    float bm = red[0];
    #pragma unroll
    for (int kk = 1; kk < 8; kk++) bm = fmaxf(bm, red[kk]);
    __syncthreads();

    v0.x = __expf(v0.x - bm); v0.y = __expf(v0.y - bm);
    v0.z = __expf(v0.z - bm); v0.w = __expf(v0.w - bm);
    v1.x = __expf(v1.x - bm); v1.y = __expf(v1.y - bm);
    v1.z = __expf(v1.z - bm); v1.w = __expf(v1.w - bm);
    float s = v0.x+v0.y+v0.z+v0.w + v1.x+v1.y+v1.z+v1.w;
    #pragma unroll
    for (int o = 16; o > 0; o >>= 1) s += __shfl_xor_sync(0xffffffffu, s, o);
    if ((tid & 31) == 0) red[tid >> 5] = s;
    __syncthreads();
    float bs = 0.f;
    #pragma unroll
    for (int kk = 0; kk < 8; kk++) bs += red[kk];
    float inv = 1.f / bs;

    v0.x *= inv; v0.y *= inv; v0.z *= inv; v0.w *= inv;
    v1.x *= inv; v1.y *= inv; v1.z *= inv; v1.w *= inv;
    r4[tid] = v0;
    r4[tid + 256] = v1;
}

// ---------------------------------------------------------------------------
// LayerNorm over D=512. One block per row, 128 threads.
// ---------------------------------------------------------------------------
__global__ __launch_bounds__(128) void ln_kernel(
    const float* __restrict__ X, const float* __restrict__ g,
    const float* __restrict__ be, float* __restrict__ O)
{
    const int tid = threadIdx.x;
    const float4* x4 = (const float4*)(X + (size_t)blockIdx.x * DD);
    float4 xv = x4[tid];
    float s  = xv.x + xv.y + xv.z + xv.w;
    float sq = xv.x*xv.x + xv.y*xv.y + xv.z*xv.z + xv.w*xv.w;
    #pragma unroll
    for (int o = 16; o > 0; o >>= 1) {
        s  += __shfl_xor_sync(0xffffffffu, s,  o);
        sq += __shfl_xor_sync(0xffffffffu, sq, o);
    }
    __shared__ float ss[4], ssq[4];
    if ((tid & 31) == 0) { ss[tid >> 5] = s; ssq[tid >> 5] = sq; }
    __syncthreads();
    s  = ss[0]  + ss[1]  + ss[2]  + ss[3];
    sq = ssq[0] + ssq[1] + ssq[2] + ssq[3];
    const float invD = 1.f / DD;
    float m = s * invD;
    float var = sq * invD - m*m;
    float rstd = rsqrtf(var + 1e-6f);
    float4 gv = ((const float4*)g)[tid];
    float4 bv = ((const float4*)be)[tid];
    float4 o;
    o.x = (xv.x - m)*rstd*gv.x + bv.x;
    o.y = (xv.y - m)*rstd*gv.y + bv.y;
    o.z = (xv.z - m)*rstd*gv.z + bv.z;
    o.w = (xv.w - m)*rstd*gv.w + bv.w;
    ((float4*)(O + (size_t)blockIdx.x * DD))[tid] = o;
}

// ===========================================================================
// Host side
// ===========================================================================
static float* scratch_ptr() {
    static float* p = nullptr;
    if (!p) cudaGetSymbolAddress((void**)&p, g_scratch);
    return p;
}

extern "C" void kernel_launch(void* const* d_in, const int* in_sizes, int n_in,
                              void* d_out, int out_size)
{
    const float* x   = (const float*)d_in[0];
    const float* enc = (const float*)d_in[1];
    const float* wq1 = (const float*)d_in[3];  const float* bq1 = (const float*)d_in[4];
    const float* wk1 = (const float*)d_in[5];  const float* bk1 = (const float*)d_in[6];
    const float* wv1 = (const float*)d_in[7];  const float* bv1 = (const float*)d_in[8];
    const float* wo1 = (const float*)d_in[9];  const float* bo1 = (const float*)d_in[10];
    const float* wq2 = (const float*)d_in[11]; const float* bq2 = (const float*)d_in[12];
    const float* wk2 = (const float*)d_in[13]; const float* bk2 = (const float*)d_in[14];
    const float* wv2 = (const float*)d_in[15]; const float* bv2 = (const float*)d_in[16];
    const float* wo2 = (const float*)d_in[17]; const float* bo2 = (const float*)d_in[18];
    const float* wf1 = (const float*)d_in[19]; const float* bf1 = (const float*)d_in[20];
    const float* wf2 = (const float*)d_in[21]; const float* bf2 = (const float*)d_in[22];
    const float* g1  = (const float*)d_in[23]; const float* be1 = (const float*)d_in[24];
    const float* g2  = (const float*)d_in[25]; const float* be2 = (const float*)d_in[26];
    const float* g3  = (const float*)d_in[27]; const float* be3 = (const float*)d_in[28];

    float* scr  = scratch_ptr();
    float* q    = scr;
    float* k    = q    + NSD;
    float* v    = k    + NSD;
    float* attn = v    + NSD;
    float* ybuf = attn + NSD;
    float* o1   = ybuf + NSD;
    float* o2   = o1   + NSD;
    float* hh   = o2   + NSD;

    float* out3 = (float*)d_out;
    float* aw1  = out3 + NSD;
    float* aw2  = aw1  + AW_ELEMS;

    const int M  = BB*SS;                // 4096
    const long long SD = (long long)SS*DD, ST = (long long)SS*TT;

    #define GEMM0(A_,sab,sah,lda, B_,sbb,sbh,ldb, C_,scb,sch,ldc, bias_,res_,ldr, Mv,Nv,Kv,Zv, sc,rl,cz) \
        tc_gemm<0><<<dim3((Nv)/64,(Mv)/128,(Zv)), 256>>>( \
            A_,sab,sah,lda, B_,sbb,sbh,ldb, C_,scb,sch,ldc, bias_,res_,ldr, Kv,sc,rl,cz)
    #define GEMM1(A_,sab,sah,lda, B_,sbb,sbh,ldb, C_,scb,sch,ldc, bias_,res_,ldr, Mv,Nv,Kv,Zv, sc,rl,cz) \
        tc_gemm<1><<<dim3((Nv)/64,(Mv)/128,(Zv)), 256>>>( \
            A_,sab,sah,lda, B_,sbb,sbh,ldb, C_,scb,sch,ldc, bias_,res_,ldr, Kv,sc,rl,cz)

    // ---- self-attention (causal) ----
    GEMM1(x,0,0,DD,  wq1,0,0,DD,  q,0,0,DD,  bq1,(const float*)nullptr,0, M,DD,DD,1, 1.f,0,0);
    GEMM1(x,0,0,DD,  wk1,0,0,DD,  k,0,0,DD,  bk1,(const float*)nullptr,0, M,DD,DD,1, 1.f,0,0);
    GEMM1(x,0,0,DD,  wv1,0,0,DD,  v,0,0,DD,  bv1,(const float*)nullptr,0, M,DD,DD,1, 1.f,0,0);
    GEMM0(q,SD,64,DD,  k,SD,64,DD,  aw1,8*ST,ST,TT,
          (const float*)nullptr,(const float*)nullptr,0, SS,TT,DKK,BB*HH, 0.125f,0,1);
    softmax_causal_kernel<<<BB*HH*SS, 256>>>(aw1);
    GEMM1(aw1,8*ST,ST,TT,  v,SD,64,DD,  attn,SD,64,DD,
          (const float*)nullptr,(const float*)nullptr,0, SS,DKK,TT,BB*HH, 1.f,0,2);
    GEMM1(attn,0,0,DD,  wo1,0,0,DD,  ybuf,0,0,DD,  bo1,x,DD, M,DD,DD,1, 1.f,0,0);
    ln_kernel<<<BB*SS, 128>>>(ybuf, g1, be1, o1);

    // ---- cross-attention (no mask) ----
    GEMM1(o1,0,0,DD,   wq2,0,0,DD,  q,0,0,DD,  bq2,(const float*)nullptr,0, M,DD,DD,1, 1.f,0,0);
    GEMM1(enc,0,0,DD,  wk2,0,0,DD,  k,0,0,DD,  bk2,(const float*)nullptr,0, M,DD,DD,1, 1.f,0,0);
    GEMM1(enc,0,0,DD,  wv2,0,0,DD,  v,0,0,DD,  bv2,(const float*)nullptr,0, M,DD,DD,1, 1.f,0,0);
    GEMM0(q,SD,64,DD,  k,SD,64,DD,  aw2,8*ST,ST,TT,
          (const float*)nullptr,(const float*)nullptr,0, SS,TT,DKK,BB*HH, 0.125f,0,0);
    softmax_kernel<<<BB*HH*SS, 256>>>(aw2);
    GEMM1(aw2,8*ST,ST,TT,  v,SD,64,DD,  attn,SD,64,DD,
          (const float*)nullptr,(const float*)nullptr,0, SS,DKK,TT,BB*HH, 1.f,0,0);
    GEMM1(attn,0,0,DD,  wo2,0,0,DD,  ybuf,0,0,DD,  bo2,o1,DD, M,DD,DD,1, 1.f,0,0);
    ln_kernel<<<BB*SS, 128>>>(ybuf, g2, be2, o2);

    // ---- FFN ----
    GEMM1(o2,0,0,DD,   wf1,0,0,FFF,  hh,0,0,FFF,  bf1,(const float*)nullptr,0, M,FFF,DD,1,  1.f,1,0);
    GEMM1(hh,0,0,FFF,  wf2,0,0,DD,   ybuf,0,0,DD, bf2,o2,DD,                   M,DD,FFF,1,  1.f,0,0);
    ln_kernel<<<BB*SS, 128>>>(ybuf, g3, be3, out3);
}

// round 10
// speedup vs baseline: 2.2975x; 1.0740x over previous
#include <cuda_runtime.h>
#include <cstdint>
#include <cstddef>

// Problem dims (fixed)
#define BB   2
#define SS   2048
#define TT   2048
#define DD   512
#define HH   8
#define DKK  64
#define FFF  2048

#define NSD  (BB*SS*DD)
#define NSF  (BB*SS*FFF)
#define AW_ELEMS ((size_t)BB*HH*(size_t)SS*TT)

// q,k,v,attn,ybuf,o1,o2 (7*NSD) + hh (NSF)
__device__ float g_scratch[7*NSD + NSF];

// ===========================================================================
// tf32 helpers (sm_80+ PTX — legal on plain sm_103 target)
// ===========================================================================
__device__ __forceinline__ void cvt4_tf32(uint32_t* t, float4 v){
  asm("cvt.rna.tf32.f32 %0, %1;":"=r"(t[0]):"f"(v.x));
  asm("cvt.rna.tf32.f32 %0, %1;":"=r"(t[1]):"f"(v.y));
  asm("cvt.rna.tf32.f32 %0, %1;":"=r"(t[2]):"f"(v.z));
  asm("cvt.rna.tf32.f32 %0, %1;":"=r"(t[3]):"f"(v.w));
}
__device__ __forceinline__ void mma_tf32(float* d, const uint32_t* a, const uint32_t* b){
  asm volatile(
    "mma.sync.aligned.m16n8k8.row.col.f32.tf32.tf32.f32 "
    "{%0,%1,%2,%3}, {%4,%5,%6,%7}, {%8,%9}, {%0,%1,%2,%3};"
    : "+f"(d[0]), "+f"(d[1]), "+f"(d[2]), "+f"(d[3])
    : "r"(a[0]), "r"(a[1]), "r"(a[2]), "r"(a[3]), "r"(b[0]), "r"(b[1]));
}

// ===========================================================================
// Warp-MMA tf32 GEMM (R9-proven core, tile-size templated):
// C = scale*(A[M,K] @ B^T) (+bias)(+res)(relu)
// Block tile 128 x NT, 8 warps, mma m16n8k8, BK=16, double-buffered smem,
// register prefetch, cvt.rna.tf32 on the smem-store path.
//   NT=64 : warps 4m x 2n, warp tile 32x32 (MT=2)   [proven R6/R9]
//   NT=128: warps 2m x 4n, warp tile 64x32 (MT=4)   [more reg reuse, less L1]
// BL=0: B given as [N,K] row-major (smem [n][k], stride 20).
// BL=1: B given as [K,N] row-major (smem [k][n], stride NT+8).
// A-fragment order (PTX ISA): a0=(g,t4) a1=(g+8,t4) a2=(g,t4+4) a3=(g+8,t4+4).
// causal: 0 none; 1 skip tiles fully above diagonal; 2 limit K to row0+128.
// Grid (N/NT, M/128, Z); z -> (zb=z>>3, zh=z&7) offsets via strides.
// Streaming stores (stcs) when bias==res==nullptr (logits / AV outputs).
// ===========================================================================
#define ASTRIDE 20

template<int BL, int NT>
__global__ __launch_bounds__(256) void tc_gemm(
    const float* __restrict__ A, long long sab, long long sah, int lda,
    const float* __restrict__ Bt, long long sbb, long long sbh, int ldb,
    float* __restrict__ C, long long scb, long long sch, int ldc,
    const float* __restrict__ bias,
    const float* __restrict__ res, int ldr,
    int K, float scale, int relu, int causal)
{
    const int row0 = blockIdx.y*128, col0 = blockIdx.x*NT;
    if (causal==1 && col0 > row0+127) return;
    const int Keff = (causal==2) ? (row0+128) : K;

    const int z = blockIdx.z, zb = z>>3, zh = z&7;
    A  += (size_t)zb*sab + (size_t)zh*sah;
    Bt += (size_t)zb*sbb + (size_t)zh*sbh;
    C  += (size_t)zb*scb + (size_t)zh*sch;

    constexpr int MT   = (NT==128) ? 4 : 2;     // m sub-tiles per warp
    constexpr int BCH  = NT/64;                 // B gmem chunks per thread
    constexpr int BST1 = NT + 8;                // BL=1 smem stride (72 / 136)
    constexpr int BS_WORDS = (BL==0) ? NT*ASTRIDE : 16*BST1;

    __shared__ uint32_t As[2][128*ASTRIDE];
    __shared__ uint32_t Bs[2][BS_WORDS];

    const int tid = threadIdx.x;
    const int wid = tid>>5, lane = tid&31;
    const int warp_m = (NT==128) ? (wid>>2) : (wid>>1);
    const int warp_n = (NT==128) ? (wid&3)  : (wid&1);
    const int mbase  = warp_m * (MT*16);
    const int g = lane>>2, t4 = lane&3;

    // gmem -> smem mapping
    const int ar = tid>>1, ak = (tid&1)*8;   // A: 128 rows x 16 k
    const float* Aptr = A + (size_t)(row0+ar)*lda + ak;

    // B mapping (per chunk c: idx = tid + c*256)
    int brow[BCH], bcol[BCH];
    const float* Bp[BCH];
    #pragma unroll
    for (int c = 0; c < BCH; c++){
        int idx = tid + c*256;
        if (BL == 0){ brow[c] = idx>>2; bcol[c] = (idx&3)*4;       // [N rows][16 k]
                      Bp[c] = Bt + (size_t)(col0+brow[c])*ldb + bcol[c]; }
        else {
            if (NT==64){ brow[c] = idx>>4; bcol[c] = (idx&15)*4; } // 16 rows x 64 n
            else       { brow[c] = idx>>5; bcol[c] = (idx&31)*4; } // 16 rows x 128 n
            Bp[c] = Bt + (size_t)brow[c]*ldb + col0 + bcol[c];
        }
    }

    float4 pa0 = *(const float4*)(Aptr);
    float4 pa1 = *(const float4*)(Aptr + 4);
    float4 pb[BCH];
    #pragma unroll
    for (int c = 0; c < BCH; c++) pb[c] = *(const float4*)(Bp[c]);

    float acc[MT][4][4] = {};
    const int nIter = Keff >> 4;

    for (int i = 0; i < nIter; i++){
        const int s = i & 1;
        const int k0 = i << 4;
        { uint32_t t[4];
          cvt4_tf32(t, pa0); *(uint4*)&As[s][ar*ASTRIDE + ak]     = *(uint4*)t;
          cvt4_tf32(t, pa1); *(uint4*)&As[s][ar*ASTRIDE + ak + 4] = *(uint4*)t;
          #pragma unroll
          for (int c = 0; c < BCH; c++){
            cvt4_tf32(t, pb[c]);
            if (BL == 0) *(uint4*)&Bs[s][brow[c]*ASTRIDE + bcol[c]] = *(uint4*)t;
            else         *(uint4*)&Bs[s][brow[c]*BST1   + bcol[c]] = *(uint4*)t;
          }
        }
        __syncthreads();
        if (i + 1 < nIter){
            pa0 = *(const float4*)(Aptr + k0 + 16);
            pa1 = *(const float4*)(Aptr + k0 + 20);
            #pragma unroll
            for (int c = 0; c < BCH; c++)
                pb[c] = (BL==0) ? *(const float4*)(Bp[c] + k0 + 16)
                                : *(const float4*)(Bp[c] + (size_t)(k0 + 16)*ldb);
        }
        #pragma unroll
        for (int ks = 0; ks < 2; ks++){
            const int kb = ks*8;
            uint32_t af[MT][4], bf[4][2];
            #pragma unroll
            for (int mt = 0; mt < MT; mt++){
                const int rA = (mbase + mt*16 + g)*ASTRIDE + kb + t4;
                af[mt][0] = As[s][rA];                      // (g,     t4)
                af[mt][1] = As[s][rA + 8*ASTRIDE];          // (g+8,   t4)
                af[mt][2] = As[s][rA + 4];                  // (g,   t4+4)
                af[mt][3] = As[s][rA + 8*ASTRIDE + 4];      // (g+8, t4+4)
            }
            if (BL == 0){
                #pragma unroll
                for (int nt = 0; nt < 4; nt++){
                    const int rB = (warp_n*32 + nt*8 + g)*ASTRIDE + kb + t4;
                    bf[nt][0] = Bs[s][rB];                  // (k=t4,   n=g)
                    bf[nt][1] = Bs[s][rB + 4];              // (k=t4+4, n=g)
                }
            } else {
                #pragma unroll
                for (int nt = 0; nt < 4; nt++){
                    const int cB = warp_n*32 + nt*8 + g;
                    bf[nt][0] = Bs[s][(kb + t4)*BST1 + cB];
                    bf[nt][1] = Bs[s][(kb + t4 + 4)*BST1 + cB];
                }
            }
            #pragma unroll
            for (int mt = 0; mt < MT; mt++)
                #pragma unroll
                for (int nt = 0; nt < 4; nt++)
                    mma_tf32(acc[mt][nt], af[mt], bf[nt]);
        }
        __syncthreads();
    }

    // Epilogue. c0=(g,2t4) c1=(g,2t4+1) c2=(g+8,2t4) c3=(g+8,2t4+1).
    const bool streaming = (bias == nullptr) && (res == nullptr);
    #pragma unroll
    for (int mt = 0; mt < MT; mt++){
        #pragma unroll
        for (int half = 0; half < 2; half++){
            const int r = row0 + mbase + mt*16 + g + half*8;
            #pragma unroll
            for (int nt = 0; nt < 4; nt++){
                const int c = col0 + warp_n*32 + nt*8 + 2*t4;
                float vx = acc[mt][nt][half*2 + 0] * scale;
                float vy = acc[mt][nt][half*2 + 1] * scale;
                if (bias){ vx += bias[c]; vy += bias[c+1]; }
                if (res){ const float* rp = &res[(size_t)r*ldr + c];
                          vx += rp[0]; vy += rp[1]; }
                if (relu){ vx = fmaxf(vx, 0.f); vy = fmaxf(vy, 0.f); }
                float2 o; o.x = vx; o.y = vy;
                float2* cp = (float2*)&C[(size_t)r*ldc + c];
                if (streaming) __stcs(cp, o); else *cp = o;
            }
        }
    }
}

// ---------------------------------------------------------------------------
// Non-causal row softmax in place (row length TT), 256 threads. Streaming.
// ---------------------------------------------------------------------------
__global__ __launch_bounds__(256) void softmax_kernel(float* __restrict__ AW)
{
    const int tid = threadIdx.x;
    float4* r4 = (float4*)(AW + (size_t)blockIdx.x * TT);
    float4 v0 = __ldcs(r4 + tid);
    float4 v1 = __ldcs(r4 + tid + 256);

    float m = fmaxf(fmaxf(fmaxf(v0.x,v0.y),fmaxf(v0.z,v0.w)),
                    fmaxf(fmaxf(v1.x,v1.y),fmaxf(v1.z,v1.w)));
    #pragma unroll
    for (int o = 16; o > 0; o >>= 1) m = fmaxf(m, __shfl_xor_sync(0xffffffffu, m, o));
    __shared__ float red[8];
    if ((tid & 31) == 0) red[tid >> 5] = m;
    __syncthreads();
    float bm = red[0];
    #pragma unroll
    for (int i = 1; i < 8; i++) bm = fmaxf(bm, red[i]);
    __syncthreads();

    v0.x = __expf(v0.x - bm); v0.y = __expf(v0.y - bm);
    v0.z = __expf(v0.z - bm); v0.w = __expf(v0.w - bm);
    v1.x = __expf(v1.x - bm); v1.y = __expf(v1.y - bm);
    v1.z = __expf(v1.z - bm); v1.w = __expf(v1.w - bm);
    float s = v0.x+v0.y+v0.z+v0.w + v1.x+v1.y+v1.z+v1.w;
    #pragma unroll
    for (int o = 16; o > 0; o >>= 1) s += __shfl_xor_sync(0xffffffffu, s, o);
    if ((tid & 31) == 0) red[tid >> 5] = s;
    __syncthreads();
    float bs = 0.f;
    #pragma unroll
    for (int i = 0; i < 8; i++) bs += red[i];
    float inv = 1.f / bs;

    v0.x *= inv; v0.y *= inv; v0.z *= inv; v0.w *= inv;
    v1.x *= inv; v1.y *= inv; v1.z *= inv; v1.w *= inv;
    __stcs(r4 + tid, v0);
    __stcs(r4 + tid + 256, v1);
}

// ---------------------------------------------------------------------------
// Causal softmax: row i uses only j<=i (masked region never read by us),
// writes exact 0 for j>i. Streaming.
// ---------------------------------------------------------------------------
__global__ __launch_bounds__(256) void softmax_causal_kernel(float* __restrict__ AW)
{
    const int tid = threadIdx.x;
    const int i = blockIdx.x & (SS - 1);
    float4* r4 = (float4*)(AW + (size_t)blockIdx.x * TT);

    const float NEG = -1e30f;
    int j0 = tid * 4, j1 = (tid + 256) * 4;
    float4 v0 = (j0 <= i) ? __ldcs(r4 + tid)       : make_float4(NEG,NEG,NEG,NEG);
    float4 v1 = (j1 <= i) ? __ldcs(r4 + tid + 256) : make_float4(NEG,NEG,NEG,NEG);
    if (j0     > i) v0.x = NEG;
    if (j0 + 1 > i) v0.y = NEG;
    if (j0 + 2 > i) v0.z = NEG;
    if (j0 + 3 > i) v0.w = NEG;
    if (j1     > i) v1.x = NEG;
    if (j1 + 1 > i) v1.y = NEG;
    if (j1 + 2 > i) v1.z = NEG;
    if (j1 + 3 > i) v1.w = NEG;

    float m = fmaxf(fmaxf(fmaxf(v0.x,v0.y),fmaxf(v0.z,v0.w)),
                    fmaxf(fmaxf(v1.x,v1.y),fmaxf(v1.z,v1.w)));
    #pragma unroll
    for (int o = 16; o > 0; o >>= 1) m = fmaxf(m, __shfl_xor_sync(0xffffffffu, m, o));
    __shared__ float red[8];
    if ((tid & 31) == 0) red[tid >> 5] = m;
    __syncthreads();
    float bm = red[0];
    #pragma unroll
    for (int kk = 1; kk < 8; kk++) bm = fmaxf(bm, red[kk]);
    __syncthreads();

    v0.x = __expf(v0.x - bm); v0.y = __expf(v0.y - bm);
    v0.z = __expf(v0.z - bm); v0.w = __expf(v0.w - bm);
    v1.x = __expf(v1.x - bm); v1.y = __expf(v1.y - bm);
    v1.z = __expf(v1.z - bm); v1.w = __expf(v1.w - bm);
    float s = v0.x+v0.y+v0.z+v0.w + v1.x+v1.y+v1.z+v1.w;
    #pragma unroll
    for (int o = 16; o > 0; o >>= 1) s += __shfl_xor_sync(0xffffffffu, s, o);
    if ((tid & 31) == 0) red[tid >> 5] = s;
    __syncthreads();
    float bs = 0.f;
    #pragma unroll
    for (int kk = 0; kk < 8; kk++) bs += red[kk];
    float inv = 1.f / bs;

    v0.x *= inv; v0.y *= inv; v0.z *= inv; v0.w *= inv;
    v1.x *= inv; v1.y *= inv; v1.z *= inv; v1.w *= inv;
    __stcs(r4 + tid, v0);
    __stcs(r4 + tid + 256, v1);
}

// ---------------------------------------------------------------------------
// LayerNorm over D=512. One block per row, 128 threads.
// ---------------------------------------------------------------------------
__global__ __launch_bounds__(128) void ln_kernel(
    const float* __restrict__ X, const float* __restrict__ g,
    const float* __restrict__ be, float* __restrict__ O)
{
    const int tid = threadIdx.x;
    const float4* x4 = (const float4*)(X + (size_t)blockIdx.x * DD);
    float4 xv = x4[tid];
    float s  = xv.x + xv.y + xv.z + xv.w;
    float sq = xv.x*xv.x + xv.y*xv.y + xv.z*xv.z + xv.w*xv.w;
    #pragma unroll
    for (int o = 16; o > 0; o >>= 1) {
        s  += __shfl_xor_sync(0xffffffffu, s,  o);
        sq += __shfl_xor_sync(0xffffffffu, sq, o);
    }
    __shared__ float ss[4], ssq[4];
    if ((tid & 31) == 0) { ss[tid >> 5] = s; ssq[tid >> 5] = sq; }
    __syncthreads();
    s  = ss[0]  + ss[1]  + ss[2]  + ss[3];
    sq = ssq[0] + ssq[1] + ssq[2] + ssq[3];
    const float invD = 1.f / DD;
    float m = s * invD;
    float var = sq * invD - m*m;
    float rstd = rsqrtf(var + 1e-6f);
    float4 gv = ((const float4*)g)[tid];
    float4 bv = ((const float4*)be)[tid];
    float4 o;
    o.x = (xv.x - m)*rstd*gv.x + bv.x;
    o.y = (xv.y - m)*rstd*gv.y + bv.y;
    o.z = (xv.z - m)*rstd*gv.z + bv.z;
    o.w = (xv.w - m)*rstd*gv.w + bv.w;
    ((float4*)(O + (size_t)blockIdx.x * DD))[tid] = o;
}

// ===========================================================================
// Host side
// ===========================================================================
static float* scratch_ptr() {
    static float* p = nullptr;
    if (!p) cudaGetSymbolAddress((void**)&p, g_scratch);
    return p;
}

extern "C" void kernel_launch(void* const* d_in, const int* in_sizes, int n_in,
                              void* d_out, int out_size)
{
    const float* x   = (const float*)d_in[0];
    const float* enc = (const float*)d_in[1];
    const float* wq1 = (const float*)d_in[3];  const float* bq1 = (const float*)d_in[4];
    const float* wk1 = (const float*)d_in[5];  const float* bk1 = (const float*)d_in[6];
    const float* wv1 = (const float*)d_in[7];  const float* bv1 = (const float*)d_in[8];
    const float* wo1 = (const float*)d_in[9];  const float* bo1 = (const float*)d_in[10];
    const float* wq2 = (const float*)d_in[11]; const float* bq2 = (const float*)d_in[12];
    const float* wk2 = (const float*)d_in[13]; const float* bk2 = (const float*)d_in[14];
    const float* wv2 = (const float*)d_in[15]; const float* bv2 = (const float*)d_in[16];
    const float* wo2 = (const float*)d_in[17]; const float* bo2 = (const float*)d_in[18];
    const float* wf1 = (const float*)d_in[19]; const float* bf1 = (const float*)d_in[20];
    const float* wf2 = (const float*)d_in[21]; const float* bf2 = (const float*)d_in[22];
    const float* g1  = (const float*)d_in[23]; const float* be1 = (const float*)d_in[24];
    const float* g2  = (const float*)d_in[25]; const float* be2 = (const float*)d_in[26];
    const float* g3  = (const float*)d_in[27]; const float* be3 = (const float*)d_in[28];

    float* scr  = scratch_ptr();
    float* q    = scr;
    float* k    = q    + NSD;
    float* v    = k    + NSD;
    float* attn = v    + NSD;
    float* ybuf = attn + NSD;
    float* o1   = ybuf + NSD;
    float* o2   = o1   + NSD;
    float* hh   = o2   + NSD;

    float* out3 = (float*)d_out;
    float* aw1  = out3 + NSD;
    float* aw2  = aw1  + AW_ELEMS;

    const int M  = BB*SS;                // 4096
    const long long SD = (long long)SS*DD, ST = (long long)SS*TT;

    // NT=128 for projections / logits / FFN; NT=64 (proven) for AV (N=64).
    #define GEMM0w(A_,sab,sah,lda, B_,sbb,sbh,ldb, C_,scb,sch,ldc, bias_,res_,ldr, Mv,Nv,Kv,Zv, sc,rl,cz) \
        tc_gemm<0,128><<<dim3((Nv)/128,(Mv)/128,(Zv)), 256>>>( \
            A_,sab,sah,lda, B_,sbb,sbh,ldb, C_,scb,sch,ldc, bias_,res_,ldr, Kv,sc,rl,cz)
    #define GEMM1w(A_,sab,sah,lda, B_,sbb,sbh,ldb, C_,scb,sch,ldc, bias_,res_,ldr, Mv,Nv,Kv,Zv, sc,rl,cz) \
        tc_gemm<1,128><<<dim3((Nv)/128,(Mv)/128,(Zv)), 256>>>( \
            A_,sab,sah,lda, B_,sbb,sbh,ldb, C_,scb,sch,ldc, bias_,res_,ldr, Kv,sc,rl,cz)
    #define GEMM1n(A_,sab,sah,lda, B_,sbb,sbh,ldb, C_,scb,sch,ldc, bias_,res_,ldr, Mv,Nv,Kv,Zv, sc,rl,cz) \
        tc_gemm<1,64><<<dim3((Nv)/64,(Mv)/128,(Zv)), 256>>>( \
            A_,sab,sah,lda, B_,sbb,sbh,ldb, C_,scb,sch,ldc, bias_,res_,ldr, Kv,sc,rl,cz)

    // ---- self-attention (causal) ----
    GEMM1w(x,0,0,DD,  wq1,0,0,DD,  q,0,0,DD,  bq1,(const float*)nullptr,0, M,DD,DD,1, 1.f,0,0);
    GEMM1w(x,0,0,DD,  wk1,0,0,DD,  k,0,0,DD,  bk1,(const float*)nullptr,0, M,DD,DD,1, 1.f,0,0);
    GEMM1w(x,0,0,DD,  wv1,0,0,DD,  v,0,0,DD,  bv1,(const float*)nullptr,0, M,DD,DD,1, 1.f,0,0);
    GEMM0w(q,SD,64,DD,  k,SD,64,DD,  aw1,8*ST,ST,TT,
           (const float*)nullptr,(const float*)nullptr,0, SS,TT,DKK,BB*HH, 0.125f,0,1);
    softmax_causal_kernel<<<BB*HH*SS, 256>>>(aw1);
    GEMM1n(aw1,8*ST,ST,TT,  v,SD,64,DD,  attn,SD,64,DD,
           (const float*)nullptr,(const float*)nullptr,0, SS,DKK,TT,BB*HH, 1.f,0,2);
    GEMM1w(attn,0,0,DD,  wo1,0,0,DD,  ybuf,0,0,DD,  bo1,x,DD, M,DD,DD,1, 1.f,0,0);
    ln_kernel<<<BB*SS, 128>>>(ybuf, g1, be1, o1);

    // ---- cross-attention (no mask) ----
    GEMM1w(o1,0,0,DD,   wq2,0,0,DD,  q,0,0,DD,  bq2,(const float*)nullptr,0, M,DD,DD,1, 1.f,0,0);
    GEMM1w(enc,0,0,DD,  wk2,0,0,DD,  k,0,0,DD,  bk2,(const float*)nullptr,0, M,DD,DD,1, 1.f,0,0);
    GEMM1w(enc,0,0,DD,  wv2,0,0,DD,  v,0,0,DD,  bv2,(const float*)nullptr,0, M,DD,DD,1, 1.f,0,0);
    GEMM0w(q,SD,64,DD,  k,SD,64,DD,  aw2,8*ST,ST,TT,
           (const float*)nullptr,(const float*)nullptr,0, SS,TT,DKK,BB*HH, 0.125f,0,0);
    softmax_kernel<<<BB*HH*SS, 256>>>(aw2);
    GEMM1n(aw2,8*ST,ST,TT,  v,SD,64,DD,  attn,SD,64,DD,
           (const float*)nullptr,(const float*)nullptr,0, SS,DKK,TT,BB*HH, 1.f,0,0);
    GEMM1w(attn,0,0,DD,  wo2,0,0,DD,  ybuf,0,0,DD,  bo2,o1,DD, M,DD,DD,1, 1.f,0,0);
    ln_kernel<<<BB*SS, 128>>>(ybuf, g2, be2, o2);

    // ---- FFN ----
    GEMM1w(o2,0,0,DD,   wf1,0,0,FFF,  hh,0,0,FFF,  bf1,(const float*)nullptr,0, M,FFF,DD,1,  1.f,1,0);
    GEMM1w(hh,0,0,FFF,  wf2,0,0,DD,   ybuf,0,0,DD, bf2,o2,DD,                   M,DD,FFF,1,  1.f,0,0);
    ln_kernel<<<BB*SS, 128>>>(ybuf, g3, be3, out3);
}